// round 11
// baseline (speedup 1.0000x reference)
#include <cuda_runtime.h>
#include <cuda_fp16.h>
#include <cuda_bf16.h>

#define N_NODES 100000
#define MAX_E   1600000
#define NB_SCAN 98             // ceil(100000/1024)
#define NG_GATHER 12500        // gather blocks (8 nodes/block)
#define NS_TILES  1563         // selfgemm tiles (64 nodes each)
#define MERGED_GRID (NG_GATHER + NS_TILES)   // 14063
#define CONV_BLOCKS 6250       // 1.6M float4 / 256

// ---------------- scratch (static device globals; no allocation) ------------
__device__ __align__(16) int     g_degi[N_NODES];
__device__ __align__(16) int     g_rowptr[N_NODES + 1];
__device__ __align__(16) int     g_fill[N_NODES];
__device__ __align__(16) int     g_blocksum[NB_SCAN + 1];
__device__ __align__(16) int     g_csr_src[MAX_E];
__device__ __align__(16) __half2 g_xh[N_NODES * 32];    // fp16 copy of x
__device__ __align__(16) float   g_sx[N_NODES * 64];    // x @ W1r^T
__device__ __align__(16) float   g_mean[N_NODES * 64];  // neighbor mean (fp32)
__device__ __align__(16) float   g_p[N_NODES * 32];     // h @ W2l^T

// ---------------- K0: convert x->fp16  ||  zero degree counters -------------
__global__ __launch_bounds__(256) void init_kernel(const float4* __restrict__ x4)
{
    int bid = blockIdx.x;
    if (bid < CONV_BLOCKS) {
        int t = bid * 256 + threadIdx.x;          // < 1.6M exactly
        float4 v = x4[t];
        g_xh[2 * t]     = __floats2half2_rn(v.x, v.y);
        g_xh[2 * t + 1] = __floats2half2_rn(v.z, v.w);
    } else {
        int t = (bid - CONV_BLOCKS) * 256 + threadIdx.x;
        if (t < N_NODES) g_degi[t] = 0;
    }
}

// ---------------- K1: count in-degrees ---------------------------------------
__global__ __launch_bounds__(256) void count_deg_kernel(
    const int* __restrict__ ei1, const int* __restrict__ ei2, int E1, int E2)
{
    int t = blockIdx.x * blockDim.x + threadIdx.x;
    int E = E1 + E2;
    if (t >= E) return;
    int d = (t < E1) ? ei1[t + E1] : ei2[(t - E1) + E2];
    atomicAdd(&g_degi[d], 1);
}

// ---------------- K2a: per-block exclusive scan (1024 items/block) ----------
__global__ __launch_bounds__(256) void scan_block_kernel()
{
    __shared__ int swarp[8];
    int tid = threadIdx.x, lane = tid & 31, wid = tid >> 5;
    int base = blockIdx.x * 1024 + tid * 4;

    int v0 = (base + 0 < N_NODES) ? g_degi[base + 0] : 0;
    int v1 = (base + 1 < N_NODES) ? g_degi[base + 1] : 0;
    int v2 = (base + 2 < N_NODES) ? g_degi[base + 2] : 0;
    int v3 = (base + 3 < N_NODES) ? g_degi[base + 3] : 0;
    int tsum = v0 + v1 + v2 + v3;

    int s = tsum;
    #pragma unroll
    for (int off = 1; off < 32; off <<= 1) {
        int t = __shfl_up_sync(0xffffffffu, s, off);
        if (lane >= off) s += t;
    }
    if (lane == 31) swarp[wid] = s;
    __syncthreads();
    if (tid == 0) {
        int r = 0;
        #pragma unroll
        for (int i = 0; i < 8; i++) { int t = swarp[i]; swarp[i] = r; r += t; }
        g_blocksum[blockIdx.x] = r;
    }
    __syncthreads();
    int excl = s - tsum + swarp[wid];
    if (base + 0 < N_NODES) g_rowptr[base + 0] = excl;
    if (base + 1 < N_NODES) g_rowptr[base + 1] = excl + v0;
    if (base + 2 < N_NODES) g_rowptr[base + 2] = excl + v0 + v1;
    if (base + 3 < N_NODES) g_rowptr[base + 3] = excl + v0 + v1 + v2;
}

// ---------------- K2b: add block offsets, init fill cursors ------------------
__global__ __launch_bounds__(256) void scan_add_kernel(int E)
{
    __shared__ int soff;
    int t = blockIdx.x * blockDim.x + threadIdx.x;
    int chunk = (blockIdx.x * 256) >> 10;
    if (threadIdx.x == 0) {
        int r = 0;
        for (int i = 0; i < chunk; i++) r += g_blocksum[i];
        soff = r;
    }
    __syncthreads();
    if (t < N_NODES) {
        int val = g_rowptr[t] + soff;
        g_rowptr[t] = val;
        g_fill[t] = val;
    }
    if (t == N_NODES) g_rowptr[N_NODES] = E;
}

// ---------------- K3: fill CSR slots -----------------------------------------
__global__ __launch_bounds__(256) void fill_csr_kernel(
    const int* __restrict__ ei1, const int* __restrict__ ei2, int E1, int E2)
{
    int t = blockIdx.x * blockDim.x + threadIdx.x;
    int E = E1 + E2;
    if (t >= E) return;
    int s, d;
    if (t < E1) { s = ei1[t];      d = ei1[t + E1]; }
    else        { int u = t - E1;  s = ei2[u];  d = ei2[u + E2]; }
    int pos = atomicAdd(&g_fill[d], 1);
    g_csr_src[pos] = s;
}

// ---------------- K4: MERGED gather64(fp16) || selfgemm ---------------------
// Every 9th block: one 64-node selfgemm tile (g_sx = x @ W1r^T).
// Other blocks: warp-per-node fp16 gather -> g_mean (fp32 accumulate).
__global__ __launch_bounds__(256) void gather_self_kernel(
    const float* __restrict__ x, const float* __restrict__ W1r)
{
    __shared__ float smem[8192];    // selfgemm: sA(4096) + sB(4096)

    int bid = blockIdx.x;
    int q = bid / 9, r = bid - q * 9;

    if (r == 0) {
        // ---------------- selfgemm tile q (q < NS_TILES always) -------------
        float* sA = smem;           // [k][node] 64x64
        float* sB = smem + 4096;    // [k][out]  64x64
        int tid = threadIdx.x;
        int node0 = q * 64;
        int tx = tid & 15, ty = tid >> 4;
        float acc[4][4] = {};

        #pragma unroll
        for (int i = 0; i < 4; i++) {
            int idx = tid + i * 256;
            int n = idx >> 4;
            int c = idx & 15;
            int gn = node0 + n;
            float4 v = (gn < N_NODES)
                ? reinterpret_cast<const float4*>(x)[gn * 16 + c]
                : make_float4(0.f, 0.f, 0.f, 0.f);
            sA[(c * 4 + 0) * 64 + n] = v.x; sA[(c * 4 + 1) * 64 + n] = v.y;
            sA[(c * 4 + 2) * 64 + n] = v.z; sA[(c * 4 + 3) * 64 + n] = v.w;
            float4 w = reinterpret_cast<const float4*>(W1r)[n * 16 + c];
            sB[(c * 4 + 0) * 64 + n] = w.x; sB[(c * 4 + 1) * 64 + n] = w.y;
            sB[(c * 4 + 2) * 64 + n] = w.z; sB[(c * 4 + 3) * 64 + n] = w.w;
        }
        __syncthreads();

        #pragma unroll 8
        for (int k = 0; k < 64; k++) {
            float4 a4 = *reinterpret_cast<const float4*>(&sA[k * 64 + ty * 4]);
            float4 b4 = *reinterpret_cast<const float4*>(&sB[k * 64 + tx * 4]);
            float a_[4] = {a4.x, a4.y, a4.z, a4.w};
            float b_[4] = {b4.x, b4.y, b4.z, b4.w};
            #pragma unroll
            for (int i = 0; i < 4; i++)
                #pragma unroll
                for (int j = 0; j < 4; j++)
                    acc[i][j] = fmaf(a_[i], b_[j], acc[i][j]);
        }

        #pragma unroll
        for (int i = 0; i < 4; i++) {
            int gn = node0 + ty * 4 + i;
            if (gn < N_NODES) {
                float4 o = make_float4(acc[i][0], acc[i][1], acc[i][2], acc[i][3]);
                reinterpret_cast<float4*>(g_sx)[gn * 16 + tx] = o;
            }
        }
    } else {
        // ---------------- gather: 8 nodes (warp per node), fp16 reads -------
        int gb = bid - q - 1;                    // 0..NG_GATHER-1
        int wid = threadIdx.x >> 5, lane = threadIdx.x & 31;
        int n = gb * 8 + wid;
        if (n >= N_NODES) return;

        int start = g_rowptr[n], end = g_rowptr[n + 1];

        float ax = 0.f, ay = 0.f;
        int e = start;
        for (; e + 4 <= end; e += 4) {
            int s0 = g_csr_src[e + 0];
            int s1 = g_csr_src[e + 1];
            int s2 = g_csr_src[e + 2];
            int s3 = g_csr_src[e + 3];
            float2 f0 = __half22float2(g_xh[s0 * 32 + lane]);
            float2 f1 = __half22float2(g_xh[s1 * 32 + lane]);
            float2 f2 = __half22float2(g_xh[s2 * 32 + lane]);
            float2 f3 = __half22float2(g_xh[s3 * 32 + lane]);
            ax += (f0.x + f1.x) + (f2.x + f3.x);
            ay += (f0.y + f1.y) + (f2.y + f3.y);
        }
        for (; e < end; e++) {
            int s = g_csr_src[e];
            float2 f = __half22float2(g_xh[s * 32 + lane]);
            ax += f.x; ay += f.y;
        }
        float dinv = (end > start) ? 1.0f / (float)(end - start) : 0.0f;
        reinterpret_cast<float2*>(g_mean)[n * 32 + lane] =
            make_float2(ax * dinv, ay * dinv);
    }
}

// ---------------- K5: gemm_rest ----------------------------------------------
// Stage A: acc = mean @ W1l^T (64 k);  h = relu(acc + g_sx + b1) -> smem
// Stage B: p = h @ W2l^T -> g_p ;  q = h @ W2r^T + b2 -> out
#define HSTRIDE 72
__global__ __launch_bounds__(256) void gemm_rest_kernel(
    const float* __restrict__ W1l, const float* __restrict__ b1,
    const float* __restrict__ W2l, const float* __restrict__ W2r,
    const float* __restrict__ b2, float* __restrict__ out)
{
    __shared__ float sAbuf[128 * HSTRIDE];
    __shared__ float sB[64][64];
    __shared__ float sb1[64];
    __shared__ float sb2[32];

    int tid = threadIdx.x;
    int node0 = blockIdx.x * 128;

    if (tid < 64) sb1[tid] = b1[tid];
    if (tid >= 64 && tid < 96) sb2[tid - 64] = b2[tid - 64];
    __syncthreads();

    int tx = tid & 15, ty = tid >> 4;
    float acc[8][4] = {};

    // Stage A: mean @ W1l^T
    #pragma unroll
    for (int i = 0; i < 8; i++) {
        int idx = tid + i * 256;
        int n = idx >> 4;
        int c = idx & 15;
        int gn = node0 + n;
        float4 v = (gn < N_NODES)
            ? reinterpret_cast<const float4*>(g_mean)[gn * 16 + c]
            : make_float4(0.f, 0.f, 0.f, 0.f);
        sAbuf[(c * 4 + 0) * 128 + n] = v.x;
        sAbuf[(c * 4 + 1) * 128 + n] = v.y;
        sAbuf[(c * 4 + 2) * 128 + n] = v.z;
        sAbuf[(c * 4 + 3) * 128 + n] = v.w;
    }
    #pragma unroll
    for (int i = 0; i < 4; i++) {
        int idx = tid + i * 256;
        int j = idx >> 4;
        int c = idx & 15;
        float4 w = reinterpret_cast<const float4*>(W1l)[j * 16 + c];
        sB[c * 4 + 0][j] = w.x; sB[c * 4 + 1][j] = w.y;
        sB[c * 4 + 2][j] = w.z; sB[c * 4 + 3][j] = w.w;
    }
    __syncthreads();

    #pragma unroll 8
    for (int k = 0; k < 64; k++) {
        float4 a4a = *reinterpret_cast<const float4*>(&sAbuf[k * 128 + ty * 8]);
        float4 a4b = *reinterpret_cast<const float4*>(&sAbuf[k * 128 + ty * 8 + 4]);
        float4 b4  = *reinterpret_cast<const float4*>(&sB[k][tx * 4]);
        float a_[8] = {a4a.x, a4a.y, a4a.z, a4a.w, a4b.x, a4b.y, a4b.z, a4b.w};
        float b_[4] = {b4.x, b4.y, b4.z, b4.w};
        #pragma unroll
        for (int i = 0; i < 8; i++)
            #pragma unroll
            for (int j = 0; j < 4; j++)
                acc[i][j] = fmaf(a_[i], b_[j], acc[i][j]);
    }
    __syncthreads();

    // h = relu(acc + sx + b1) -> sAbuf[node][k]; zero acc for reuse
    #pragma unroll
    for (int i = 0; i < 8; i++) {
        int n = ty * 8 + i;
        int gn = node0 + n;
        float4 s4 = (gn < N_NODES)
            ? reinterpret_cast<const float4*>(g_sx)[gn * 16 + tx]
            : make_float4(0.f, 0.f, 0.f, 0.f);
        float4 hv;
        hv.x = fmaxf(acc[i][0] + s4.x + sb1[tx * 4 + 0], 0.f);
        hv.y = fmaxf(acc[i][1] + s4.y + sb1[tx * 4 + 1], 0.f);
        hv.z = fmaxf(acc[i][2] + s4.z + sb1[tx * 4 + 2], 0.f);
        hv.w = fmaxf(acc[i][3] + s4.w + sb1[tx * 4 + 3], 0.f);
        *reinterpret_cast<float4*>(&sAbuf[n * HSTRIDE + tx * 4]) = hv;
        acc[i][0] = acc[i][1] = acc[i][2] = acc[i][3] = 0.f;
    }

    // stacked W2 (rows 0..31: W2l, 32..63: W2r)
    #pragma unroll
    for (int i = 0; i < 4; i++) {
        int idx = tid + i * 256;
        int j = idx >> 4;
        int c = idx & 15;
        const float* Bsrc = (j < 32) ? (W2l + j * 64) : (W2r + (j - 32) * 64);
        float4 w = reinterpret_cast<const float4*>(Bsrc)[c];
        sB[c * 4 + 0][j] = w.x; sB[c * 4 + 1][j] = w.y;
        sB[c * 4 + 2][j] = w.z; sB[c * 4 + 3][j] = w.w;
    }
    __syncthreads();

    // Stage B
    for (int k0 = 0; k0 < 64; k0 += 4) {
        float4 av[8];
        #pragma unroll
        for (int i = 0; i < 8; i++)
            av[i] = *reinterpret_cast<const float4*>(
                        &sAbuf[(ty * 8 + i) * HSTRIDE + k0]);
        #pragma unroll
        for (int kk = 0; kk < 4; kk++) {
            float4 b4 = *reinterpret_cast<const float4*>(&sB[k0 + kk][tx * 4]);
            float b_[4] = {b4.x, b4.y, b4.z, b4.w};
            #pragma unroll
            for (int i = 0; i < 8; i++) {
                float a = (kk == 0) ? av[i].x : (kk == 1) ? av[i].y
                         : (kk == 2) ? av[i].z : av[i].w;
                #pragma unroll
                for (int j = 0; j < 4; j++)
                    acc[i][j] = fmaf(a, b_[j], acc[i][j]);
            }
        }
    }

    #pragma unroll
    for (int i = 0; i < 8; i++) {
        int gn = node0 + ty * 8 + i;
        if (gn < N_NODES) {
            if (tx < 8) {
                float4 o = make_float4(acc[i][0], acc[i][1], acc[i][2], acc[i][3]);
                reinterpret_cast<float4*>(g_p)[gn * 8 + tx] = o;
            } else {
                int jc = (tx - 8) * 4;
                float4 o;
                o.x = acc[i][0] + sb2[jc + 0];
                o.y = acc[i][1] + sb2[jc + 1];
                o.z = acc[i][2] + sb2[jc + 2];
                o.w = acc[i][3] + sb2[jc + 3];
                reinterpret_cast<float4*>(out)[gn * 8 + (tx - 8)] = o;
            }
        }
    }
}

// ---------------- K6: gather layer 2 (warp per node) -------------------------
__global__ __launch_bounds__(256) void gather32_kernel(float* __restrict__ out)
{
    int wid = threadIdx.x >> 5, lane = threadIdx.x & 31;
    int n = blockIdx.x * 8 + wid;
    if (n >= N_NODES) return;

    int start = g_rowptr[n], end = g_rowptr[n + 1];

    float a = 0.f;
    int e = start;
    for (; e + 4 <= end; e += 4) {
        int s0 = g_csr_src[e + 0];
        int s1 = g_csr_src[e + 1];
        int s2 = g_csr_src[e + 2];
        int s3 = g_csr_src[e + 3];
        float v0 = __ldg(&g_p[s0 * 32 + lane]);
        float v1 = __ldg(&g_p[s1 * 32 + lane]);
        float v2 = __ldg(&g_p[s2 * 32 + lane]);
        float v3 = __ldg(&g_p[s3 * 32 + lane]);
        a += (v0 + v1) + (v2 + v3);
    }
    for (; e < end; e++) {
        int s = g_csr_src[e];
        a += __ldg(&g_p[s * 32 + lane]);
    }
    float dinv = (end > start) ? 1.0f / (float)(end - start) : 0.0f;
    out[n * 32 + lane] += a * dinv;
}

// ---------------- launch ------------------------------------------------------
extern "C" void kernel_launch(void* const* d_in, const int* in_sizes, int n_in,
                              void* d_out, int out_size)
{
    const float* x    = (const float*)d_in[0];
    const int*   ei1  = (const int*)d_in[1];     // int32 (JAX x64 disabled)
    const int*   ei2  = (const int*)d_in[3];
    const float* W1l  = (const float*)d_in[5];
    const float* b1   = (const float*)d_in[6];
    const float* W1r  = (const float*)d_in[7];
    const float* W2l  = (const float*)d_in[8];
    const float* b2   = (const float*)d_in[9];
    const float* W2r  = (const float*)d_in[10];
    float*       out  = (float*)d_out;

    int E1 = in_sizes[1] / 2;
    int E2 = in_sizes[3] / 2;
    int E  = E1 + E2;

    // K0: x->fp16 || zero degrees
    init_kernel<<<CONV_BLOCKS + (N_NODES + 255) / 256, 256>>>(
        reinterpret_cast<const float4*>(x));

    // CSR build
    count_deg_kernel<<<(E + 255) / 256, 256>>>(ei1, ei2, E1, E2);
    scan_block_kernel<<<NB_SCAN, 256>>>();
    scan_add_kernel<<<(N_NODES + 256) / 256, 256>>>(E);
    fill_csr_kernel<<<(E + 255) / 256, 256>>>(ei1, ei2, E1, E2);

    // merged: layer-1 gather (fp16) || selfgemm (x @ W1r^T)
    gather_self_kernel<<<MERGED_GRID, 256>>>(x, W1r);

    // gemm_rest -> g_p, out(self term)
    gemm_rest_kernel<<<(N_NODES + 127) / 128, 256>>>(W1l, b1, W2l, W2r, b2, out);

    // layer-2 aggregation
    gather32_kernel<<<(N_NODES + 7) / 8, 256>>>(out);
}

// round 12
// speedup vs baseline: 1.1225x; 1.1225x over previous
#include <cuda_runtime.h>
#include <cuda_fp16.h>
#include <cuda_bf16.h>

#define N_NODES 100000
#define MAX_E   1600000
#define NB_SCAN 98             // ceil(100000/1024)
#define CONV_BLOCKS 6250       // 1.6M float4 / 256

// ---------------- scratch (static device globals; no allocation) ------------
__device__ __align__(16) int     g_degi[N_NODES];
__device__ __align__(16) int     g_rowptr[N_NODES + 1];
__device__ __align__(16) int     g_fill[N_NODES];
__device__ __align__(16) int     g_blocksum[NB_SCAN + 1];
__device__ __align__(16) int     g_csr_src[MAX_E];
__device__ __align__(16) __half2 g_xh[N_NODES * 32];    // fp16 copy of x
__device__ __align__(16) float   g_mean[N_NODES * 64];  // neighbor mean (fp32)
__device__ __align__(16) float   g_p[N_NODES * 32];     // h @ W2l^T

// ---------------- K0: convert x->fp16  ||  zero degree counters -------------
__global__ __launch_bounds__(256) void init_kernel(const float4* __restrict__ x4)
{
    int bid = blockIdx.x;
    if (bid < CONV_BLOCKS) {
        int t = bid * 256 + threadIdx.x;          // < 1.6M exactly
        float4 v = x4[t];
        g_xh[2 * t]     = __floats2half2_rn(v.x, v.y);
        g_xh[2 * t + 1] = __floats2half2_rn(v.z, v.w);
    } else {
        int t = (bid - CONV_BLOCKS) * 256 + threadIdx.x;
        if (t < N_NODES) g_degi[t] = 0;
    }
}

// ---------------- K1: count in-degrees ---------------------------------------
__global__ __launch_bounds__(256) void count_deg_kernel(
    const int* __restrict__ ei1, const int* __restrict__ ei2, int E1, int E2)
{
    int t = blockIdx.x * blockDim.x + threadIdx.x;
    int E = E1 + E2;
    if (t >= E) return;
    int d = (t < E1) ? ei1[t + E1] : ei2[(t - E1) + E2];
    atomicAdd(&g_degi[d], 1);
}

// ---------------- K2a: per-block exclusive scan (1024 items/block) ----------
__global__ __launch_bounds__(256) void scan_block_kernel()
{
    __shared__ int swarp[8];
    int tid = threadIdx.x, lane = tid & 31, wid = tid >> 5;
    int base = blockIdx.x * 1024 + tid * 4;

    int v0 = (base + 0 < N_NODES) ? g_degi[base + 0] : 0;
    int v1 = (base + 1 < N_NODES) ? g_degi[base + 1] : 0;
    int v2 = (base + 2 < N_NODES) ? g_degi[base + 2] : 0;
    int v3 = (base + 3 < N_NODES) ? g_degi[base + 3] : 0;
    int tsum = v0 + v1 + v2 + v3;

    int s = tsum;
    #pragma unroll
    for (int off = 1; off < 32; off <<= 1) {
        int t = __shfl_up_sync(0xffffffffu, s, off);
        if (lane >= off) s += t;
    }
    if (lane == 31) swarp[wid] = s;
    __syncthreads();
    if (tid == 0) {
        int r = 0;
        #pragma unroll
        for (int i = 0; i < 8; i++) { int t = swarp[i]; swarp[i] = r; r += t; }
        g_blocksum[blockIdx.x] = r;
    }
    __syncthreads();
    int excl = s - tsum + swarp[wid];
    if (base + 0 < N_NODES) g_rowptr[base + 0] = excl;
    if (base + 1 < N_NODES) g_rowptr[base + 1] = excl + v0;
    if (base + 2 < N_NODES) g_rowptr[base + 2] = excl + v0 + v1;
    if (base + 3 < N_NODES) g_rowptr[base + 3] = excl + v0 + v1 + v2;
}

// ---------------- K2b: add block offsets, init fill cursors ------------------
__global__ __launch_bounds__(256) void scan_add_kernel(int E)
{
    __shared__ int soff;
    int t = blockIdx.x * blockDim.x + threadIdx.x;
    int chunk = (blockIdx.x * 256) >> 10;
    if (threadIdx.x == 0) {
        int r = 0;
        for (int i = 0; i < chunk; i++) r += g_blocksum[i];
        soff = r;
    }
    __syncthreads();
    if (t < N_NODES) {
        int val = g_rowptr[t] + soff;
        g_rowptr[t] = val;
        g_fill[t] = val;
    }
    if (t == N_NODES) g_rowptr[N_NODES] = E;
}

// ---------------- K3: fill CSR slots -----------------------------------------
__global__ __launch_bounds__(256) void fill_csr_kernel(
    const int* __restrict__ ei1, const int* __restrict__ ei2, int E1, int E2)
{
    int t = blockIdx.x * blockDim.x + threadIdx.x;
    int E = E1 + E2;
    if (t >= E) return;
    int s, d;
    if (t < E1) { s = ei1[t];      d = ei1[t + E1]; }
    else        { int u = t - E1;  s = ei2[u];  d = ei2[u + E2]; }
    int pos = atomicAdd(&g_fill[d], 1);
    g_csr_src[pos] = s;
}

// ---------------- K4: gather layer 1 (warp per node, fp16 reads) ------------
__global__ __launch_bounds__(256) void gather64_kernel()
{
    int wid = threadIdx.x >> 5, lane = threadIdx.x & 31;
    int n = blockIdx.x * 8 + wid;
    if (n >= N_NODES) return;

    int start = g_rowptr[n], end = g_rowptr[n + 1];

    float ax = 0.f, ay = 0.f;
    int e = start;
    for (; e + 4 <= end; e += 4) {
        int s0 = g_csr_src[e + 0];
        int s1 = g_csr_src[e + 1];
        int s2 = g_csr_src[e + 2];
        int s3 = g_csr_src[e + 3];
        float2 f0 = __half22float2(g_xh[s0 * 32 + lane]);
        float2 f1 = __half22float2(g_xh[s1 * 32 + lane]);
        float2 f2 = __half22float2(g_xh[s2 * 32 + lane]);
        float2 f3 = __half22float2(g_xh[s3 * 32 + lane]);
        ax += (f0.x + f1.x) + (f2.x + f3.x);
        ay += (f0.y + f1.y) + (f2.y + f3.y);
    }
    for (; e < end; e++) {
        int s = g_csr_src[e];
        float2 f = __half22float2(g_xh[s * 32 + lane]);
        ax += f.x; ay += f.y;
    }
    float dinv = (end > start) ? 1.0f / (float)(end - start) : 0.0f;
    reinterpret_cast<float2*>(g_mean)[n * 32 + lane] =
        make_float2(ax * dinv, ay * dinv);
}

// ---------------- K5: fused two-layer GEMM (round-10 proven version) --------
// Per block: 128 nodes, 256 threads, 8x4 register tile.
// Stage A operand tile: [k][node] (stride 128).  h tile: [node][k] (stride 72)
#define HSTRIDE 72
__global__ __launch_bounds__(256) void fused_gemm_kernel(
    const float* __restrict__ x,
    const float* __restrict__ W1l, const float* __restrict__ W1r,
    const float* __restrict__ b1,
    const float* __restrict__ W2l, const float* __restrict__ W2r,
    const float* __restrict__ b2,
    float* __restrict__ out)
{
    __shared__ float sAbuf[128 * HSTRIDE];
    __shared__ float sB[64][64];
    __shared__ float sb1[64];
    __shared__ float sb2[32];

    int tid = threadIdx.x;
    int node0 = blockIdx.x * 128;

    if (tid < 64) sb1[tid] = b1[tid];
    if (tid >= 64 && tid < 96) sb2[tid - 64] = b2[tid - 64];
    __syncthreads();

    int tx = tid & 15, ty = tid >> 4;
    float acc[8][4] = {};

    // ---------------- Stage A: layer-1 GEMM ([k][node], stride 128) ---------
    #pragma unroll
    for (int stage = 0; stage < 2; stage++) {
        const float* Asrc = stage ? x : g_mean;
        const float* Bsrc = stage ? W1r : W1l;
        #pragma unroll
        for (int i = 0; i < 8; i++) {
            int idx = tid + i * 256;
            int n = idx >> 4;
            int c = idx & 15;
            int gn = node0 + n;
            float4 v = (gn < N_NODES)
                ? reinterpret_cast<const float4*>(Asrc)[gn * 16 + c]
                : make_float4(0.f, 0.f, 0.f, 0.f);
            sAbuf[(c * 4 + 0) * 128 + n] = v.x;
            sAbuf[(c * 4 + 1) * 128 + n] = v.y;
            sAbuf[(c * 4 + 2) * 128 + n] = v.z;
            sAbuf[(c * 4 + 3) * 128 + n] = v.w;
        }
        #pragma unroll
        for (int i = 0; i < 4; i++) {
            int idx = tid + i * 256;
            int j = idx >> 4;
            int c = idx & 15;
            float4 w = reinterpret_cast<const float4*>(Bsrc)[j * 16 + c];
            sB[c * 4 + 0][j] = w.x; sB[c * 4 + 1][j] = w.y;
            sB[c * 4 + 2][j] = w.z; sB[c * 4 + 3][j] = w.w;
        }
        __syncthreads();

        #pragma unroll 8
        for (int k = 0; k < 64; k++) {
            float4 a4a = *reinterpret_cast<const float4*>(&sAbuf[k * 128 + ty * 8]);
            float4 a4b = *reinterpret_cast<const float4*>(&sAbuf[k * 128 + ty * 8 + 4]);
            float4 b4  = *reinterpret_cast<const float4*>(&sB[k][tx * 4]);
            float a_[8] = {a4a.x, a4a.y, a4a.z, a4a.w, a4b.x, a4b.y, a4b.z, a4b.w};
            float b_[4] = {b4.x, b4.y, b4.z, b4.w};
            #pragma unroll
            for (int i = 0; i < 8; i++)
                #pragma unroll
                for (int j = 0; j < 4; j++)
                    acc[i][j] = fmaf(a_[i], b_[j], acc[i][j]);
        }
        __syncthreads();
    }

    // relu + bias, write h as [node][k] with float4 stores; zero acc for reuse
    #pragma unroll
    for (int i = 0; i < 8; i++) {
        int n = ty * 8 + i;
        float4 hv;
        hv.x = fmaxf(acc[i][0] + sb1[tx * 4 + 0], 0.f);
        hv.y = fmaxf(acc[i][1] + sb1[tx * 4 + 1], 0.f);
        hv.z = fmaxf(acc[i][2] + sb1[tx * 4 + 2], 0.f);
        hv.w = fmaxf(acc[i][3] + sb1[tx * 4 + 3], 0.f);
        *reinterpret_cast<float4*>(&sAbuf[n * HSTRIDE + tx * 4]) = hv;
        acc[i][0] = acc[i][1] = acc[i][2] = acc[i][3] = 0.f;
    }

    // load stacked W2 (rows 0..31: W2l, 32..63: W2r) into sB[k][out]
    #pragma unroll
    for (int i = 0; i < 4; i++) {
        int idx = tid + i * 256;
        int j = idx >> 4;
        int c = idx & 15;
        const float* Bsrc = (j < 32) ? (W2l + j * 64) : (W2r + (j - 32) * 64);
        float4 w = reinterpret_cast<const float4*>(Bsrc)[c];
        sB[c * 4 + 0][j] = w.x; sB[c * 4 + 1][j] = w.y;
        sB[c * 4 + 2][j] = w.z; sB[c * 4 + 3][j] = w.w;
    }
    __syncthreads();

    // ---------------- Stage B: layer-2 GEMM (h[node][k], k-chunked x4) ------
    for (int k0 = 0; k0 < 64; k0 += 4) {
        float4 av[8];
        #pragma unroll
        for (int i = 0; i < 8; i++)
            av[i] = *reinterpret_cast<const float4*>(
                        &sAbuf[(ty * 8 + i) * HSTRIDE + k0]);
        #pragma unroll
        for (int kk = 0; kk < 4; kk++) {
            float4 b4 = *reinterpret_cast<const float4*>(&sB[k0 + kk][tx * 4]);
            float b_[4] = {b4.x, b4.y, b4.z, b4.w};
            #pragma unroll
            for (int i = 0; i < 8; i++) {
                float a = (kk == 0) ? av[i].x : (kk == 1) ? av[i].y
                         : (kk == 2) ? av[i].z : av[i].w;
                #pragma unroll
                for (int j = 0; j < 4; j++)
                    acc[i][j] = fmaf(a, b_[j], acc[i][j]);
            }
        }
    }

    #pragma unroll
    for (int i = 0; i < 8; i++) {
        int gn = node0 + ty * 8 + i;
        if (gn < N_NODES) {
            if (tx < 8) {               // p columns -> g_p
                float4 o = make_float4(acc[i][0], acc[i][1], acc[i][2], acc[i][3]);
                reinterpret_cast<float4*>(g_p)[gn * 8 + tx] = o;
            } else {                    // q columns -> out (self term + b2)
                int jc = (tx - 8) * 4;
                float4 o;
                o.x = acc[i][0] + sb2[jc + 0];
                o.y = acc[i][1] + sb2[jc + 1];
                o.z = acc[i][2] + sb2[jc + 2];
                o.w = acc[i][3] + sb2[jc + 3];
                reinterpret_cast<float4*>(out)[gn * 8 + (tx - 8)] = o;
            }
        }
    }
}

// ---------------- K6: gather layer 2 (warp per node) -------------------------
__global__ __launch_bounds__(256) void gather32_kernel(float* __restrict__ out)
{
    int wid = threadIdx.x >> 5, lane = threadIdx.x & 31;
    int n = blockIdx.x * 8 + wid;
    if (n >= N_NODES) return;

    int start = g_rowptr[n], end = g_rowptr[n + 1];

    float a = 0.f;
    int e = start;
    for (; e + 4 <= end; e += 4) {
        int s0 = g_csr_src[e + 0];
        int s1 = g_csr_src[e + 1];
        int s2 = g_csr_src[e + 2];
        int s3 = g_csr_src[e + 3];
        float v0 = __ldg(&g_p[s0 * 32 + lane]);
        float v1 = __ldg(&g_p[s1 * 32 + lane]);
        float v2 = __ldg(&g_p[s2 * 32 + lane]);
        float v3 = __ldg(&g_p[s3 * 32 + lane]);
        a += (v0 + v1) + (v2 + v3);
    }
    for (; e < end; e++) {
        int s = g_csr_src[e];
        a += __ldg(&g_p[s * 32 + lane]);
    }
    float dinv = (end > start) ? 1.0f / (float)(end - start) : 0.0f;
    out[n * 32 + lane] += a * dinv;
}

// ---------------- launch ------------------------------------------------------
extern "C" void kernel_launch(void* const* d_in, const int* in_sizes, int n_in,
                              void* d_out, int out_size)
{
    const float* x    = (const float*)d_in[0];
    const int*   ei1  = (const int*)d_in[1];     // int32 (JAX x64 disabled)
    const int*   ei2  = (const int*)d_in[3];
    const float* W1l  = (const float*)d_in[5];
    const float* b1   = (const float*)d_in[6];
    const float* W1r  = (const float*)d_in[7];
    const float* W2l  = (const float*)d_in[8];
    const float* b2   = (const float*)d_in[9];
    const float* W2r  = (const float*)d_in[10];
    float*       out  = (float*)d_out;

    int E1 = in_sizes[1] / 2;
    int E2 = in_sizes[3] / 2;
    int E  = E1 + E2;

    // K0: x->fp16 || zero degrees
    init_kernel<<<CONV_BLOCKS + (N_NODES + 255) / 256, 256>>>(
        reinterpret_cast<const float4*>(x));

    // CSR build
    count_deg_kernel<<<(E + 255) / 256, 256>>>(ei1, ei2, E1, E2);
    scan_block_kernel<<<NB_SCAN, 256>>>();
    scan_add_kernel<<<(N_NODES + 256) / 256, 256>>>(E);
    fill_csr_kernel<<<(E + 255) / 256, 256>>>(ei1, ei2, E1, E2);

    // layer-1 aggregation (gather, fp16 reads, no atomics, no extra smem)
    gather64_kernel<<<(N_NODES + 7) / 8, 256>>>();

    // fused two-layer GEMM -> g_p, out(self term)
    fused_gemm_kernel<<<(N_NODES + 127) / 128, 256>>>(
        x, W1l, W1r, b1, W2l, W2r, b2, out);

    // layer-2 aggregation
    gather32_kernel<<<(N_NODES + 7) / 8, 256>>>(out);
}

// round 14
// speedup vs baseline: 1.7322x; 1.5431x over previous
#include <cuda_runtime.h>
#include <cuda_fp16.h>
#include <cuda_bf16.h>
#include <cstdint>

#define N_NODES 100000
#define MAX_E   1600000
#define NB_SCAN 98             // ceil(100000/1024)
#define CONV_BLOCKS 6250       // 1.6M float4 / 256
#define DEG_BLOCKS  391        // ceil(100000/256)
#define APAD 72                // smem row stride in halves (144 B = 9*16B)

// ---------------- scratch (static device globals; no allocation) ------------
__device__ __align__(16) int     g_degi[N_NODES];
__device__ __align__(16) int     g_rowptr[N_NODES + 1];
__device__ __align__(16) int     g_fill[N_NODES];
__device__ __align__(16) int     g_blocksum[NB_SCAN + 1];
__device__ __align__(16) int     g_csr_src[MAX_E];
__device__ __align__(16) __half2 g_xh[N_NODES * 32];     // fp16 copy of x
__device__ __align__(16) __half2 g_meanh[N_NODES * 32];  // fp16 neighbor mean
__device__ __align__(16) __half  g_w1lh[64 * 64];
__device__ __align__(16) __half  g_w1rh[64 * 64];
__device__ __align__(16) __half  g_w2h[64 * 64];         // rows 0-31 W2l, 32-63 W2r
__device__ __align__(16) float   g_p[N_NODES * 32];      // h @ W2l^T

__device__ __forceinline__ uint32_t smem_u32(const void* p) {
    return (uint32_t)__cvta_generic_to_shared(p);
}

// ---------------- K0: x->fp16 || zero degrees || weights->fp16 --------------
__global__ __launch_bounds__(256) void init_kernel(
    const float4* __restrict__ x4,
    const float* __restrict__ W1l, const float* __restrict__ W1r,
    const float* __restrict__ W2l, const float* __restrict__ W2r)
{
    int bid = blockIdx.x;
    if (bid < CONV_BLOCKS) {
        int t = bid * 256 + threadIdx.x;          // < 1.6M exactly
        float4 v = x4[t];
        g_xh[2 * t]     = __floats2half2_rn(v.x, v.y);
        g_xh[2 * t + 1] = __floats2half2_rn(v.z, v.w);
    } else if (bid < CONV_BLOCKS + DEG_BLOCKS) {
        int t = (bid - CONV_BLOCKS) * 256 + threadIdx.x;
        if (t < N_NODES) g_degi[t] = 0;
    } else {
        int t = threadIdx.x;
        for (int i = t; i < 4096; i += 256) {
            g_w1lh[i] = __float2half_rn(W1l[i]);
            g_w1rh[i] = __float2half_rn(W1r[i]);
        }
        for (int i = t; i < 2048; i += 256) {
            g_w2h[i]        = __float2half_rn(W2l[i]);   // rows 0..31
            g_w2h[2048 + i] = __float2half_rn(W2r[i]);   // rows 32..63
        }
    }
}

// ---------------- K1: count in-degrees ---------------------------------------
__global__ __launch_bounds__(256) void count_deg_kernel(
    const int* __restrict__ ei1, const int* __restrict__ ei2, int E1, int E2)
{
    int t = blockIdx.x * blockDim.x + threadIdx.x;
    int E = E1 + E2;
    if (t >= E) return;
    int d = (t < E1) ? ei1[t + E1] : ei2[(t - E1) + E2];
    atomicAdd(&g_degi[d], 1);
}

// ---------------- K2a: per-block exclusive scan (1024 items/block) ----------
__global__ __launch_bounds__(256) void scan_block_kernel()
{
    __shared__ int swarp[8];
    int tid = threadIdx.x, lane = tid & 31, wid = tid >> 5;
    int base = blockIdx.x * 1024 + tid * 4;

    int v0 = (base + 0 < N_NODES) ? g_degi[base + 0] : 0;
    int v1 = (base + 1 < N_NODES) ? g_degi[base + 1] : 0;
    int v2 = (base + 2 < N_NODES) ? g_degi[base + 2] : 0;
    int v3 = (base + 3 < N_NODES) ? g_degi[base + 3] : 0;
    int tsum = v0 + v1 + v2 + v3;

    int s = tsum;
    #pragma unroll
    for (int off = 1; off < 32; off <<= 1) {
        int t = __shfl_up_sync(0xffffffffu, s, off);
        if (lane >= off) s += t;
    }
    if (lane == 31) swarp[wid] = s;
    __syncthreads();
    if (tid == 0) {
        int r = 0;
        #pragma unroll
        for (int i = 0; i < 8; i++) { int t = swarp[i]; swarp[i] = r; r += t; }
        g_blocksum[blockIdx.x] = r;
    }
    __syncthreads();
    int excl = s - tsum + swarp[wid];
    if (base + 0 < N_NODES) g_rowptr[base + 0] = excl;
    if (base + 1 < N_NODES) g_rowptr[base + 1] = excl + v0;
    if (base + 2 < N_NODES) g_rowptr[base + 2] = excl + v0 + v1;
    if (base + 3 < N_NODES) g_rowptr[base + 3] = excl + v0 + v1 + v2;
}

// ---------------- K2b: add block offsets, init fill cursors ------------------
__global__ __launch_bounds__(256) void scan_add_kernel(int E)
{
    __shared__ int soff;
    int t = blockIdx.x * blockDim.x + threadIdx.x;
    int chunk = (blockIdx.x * 256) >> 10;
    if (threadIdx.x == 0) {
        int r = 0;
        for (int i = 0; i < chunk; i++) r += g_blocksum[i];
        soff = r;
    }
    __syncthreads();
    if (t < N_NODES) {
        int val = g_rowptr[t] + soff;
        g_rowptr[t] = val;
        g_fill[t] = val;
    }
    if (t == N_NODES) g_rowptr[N_NODES] = E;
}

// ---------------- K3: fill CSR slots -----------------------------------------
__global__ __launch_bounds__(256) void fill_csr_kernel(
    const int* __restrict__ ei1, const int* __restrict__ ei2, int E1, int E2)
{
    int t = blockIdx.x * blockDim.x + threadIdx.x;
    int E = E1 + E2;
    if (t >= E) return;
    int s, d;
    if (t < E1) { s = ei1[t];      d = ei1[t + E1]; }
    else        { int u = t - E1;  s = ei2[u];  d = ei2[u + E2]; }
    int pos = atomicAdd(&g_fill[d], 1);
    g_csr_src[pos] = s;
}

// ---------------- K4: gather layer 1 (warp per node, fp16 in/out) -----------
__global__ __launch_bounds__(256) void gather64_kernel()
{
    int wid = threadIdx.x >> 5, lane = threadIdx.x & 31;
    int n = blockIdx.x * 8 + wid;
    if (n >= N_NODES) return;

    int start = g_rowptr[n], end = g_rowptr[n + 1];

    float ax = 0.f, ay = 0.f;
    int e = start;
    for (; e + 4 <= end; e += 4) {
        int s0 = g_csr_src[e + 0];
        int s1 = g_csr_src[e + 1];
        int s2 = g_csr_src[e + 2];
        int s3 = g_csr_src[e + 3];
        float2 f0 = __half22float2(g_xh[s0 * 32 + lane]);
        float2 f1 = __half22float2(g_xh[s1 * 32 + lane]);
        float2 f2 = __half22float2(g_xh[s2 * 32 + lane]);
        float2 f3 = __half22float2(g_xh[s3 * 32 + lane]);
        ax += (f0.x + f1.x) + (f2.x + f3.x);
        ay += (f0.y + f1.y) + (f2.y + f3.y);
    }
    for (; e < end; e++) {
        int s = g_csr_src[e];
        float2 f = __half22float2(g_xh[s * 32 + lane]);
        ax += f.x; ay += f.y;
    }
    float dinv = (end > start) ? 1.0f / (float)(end - start) : 0.0f;
    g_meanh[n * 32 + lane] = __floats2half2_rn(ax * dinv, ay * dinv);
}

// ---------------- K5: fused two-layer GEMM on tensor cores (HMMA) -----------
// Block: 128 nodes x 64 outs, 8 warps; warp w owns node rows [w*16, w*16+16).
// mma.m16n8k16.f32.f16.f16.f32; A=[node][k], W=[out][k] (both ldmatrix non-trans)
// computes sum_k A(m,k)*W(n,k) = A @ W^T.
__global__ __launch_bounds__(256) void fused_mma_kernel(
    const float* __restrict__ b1, const float* __restrict__ b2,
    float* __restrict__ out)
{
    __shared__ __half sA[128 * APAD];   // operand / h tile (18432 B)
    __shared__ __half sW[64 * APAD];    // weight tile (9216 B)
    __shared__ float  sb1[64];
    __shared__ float  sb2[32];

    int tid = threadIdx.x;
    int warp = tid >> 5, lane = tid & 31;
    int grp = lane >> 2, tig = lane & 3;
    int node0 = blockIdx.x * 128;

    if (tid < 64) sb1[tid] = b1[tid];
    if (tid >= 64 && tid < 96) sb2[tid - 64] = b2[tid - 64];

    // ldmatrix lane addressing
    int a_row  = lane & 15;               // m-row within warp tile
    int a_koff = (lane >> 4) * 8;         // halves
    int b_row  = lane & 7;                // n-row
    int b_koff = ((lane >> 3) & 1) * 8;   // halves (lanes 0-15 used by x2)

    uint32_t a_base = smem_u32(&sA[(warp * 16 + a_row) * APAD + a_koff]);
    uint32_t b_base = smem_u32(&sW[b_row * APAD + b_koff]);

    float acc[8][4] = {};   // 8 n-tiles x 4 f32

    // ---------------- layer 1: two K=64 stages ------------------------------
    #pragma unroll
    for (int stage = 0; stage < 2; stage++) {
        const uint4* Asrc = reinterpret_cast<const uint4*>(stage ? g_xh : g_meanh);
        const uint4* Wsrc = reinterpret_cast<const uint4*>(stage ? g_w1rh : g_w1lh);
        #pragma unroll
        for (int i = 0; i < 4; i++) {                  // A: 128 rows x 8 uint4
            int idx = tid + i * 256;
            int n = idx >> 3, c = idx & 7;
            int gn = node0 + n;
            uint4 v = (gn < N_NODES) ? Asrc[gn * 8 + c] : make_uint4(0, 0, 0, 0);
            *reinterpret_cast<uint4*>(&sA[n * APAD + c * 8]) = v;
        }
        #pragma unroll
        for (int i = 0; i < 2; i++) {                  // W: 64 rows x 8 uint4
            int idx = tid + i * 256;
            int j = idx >> 3, c = idx & 7;
            *reinterpret_cast<uint4*>(&sW[j * APAD + c * 8]) = Wsrc[j * 8 + c];
        }
        __syncthreads();

        #pragma unroll
        for (int k0 = 0; k0 < 64; k0 += 16) {
            uint32_t a0, a1, a2, a3;
            asm volatile(
                "ldmatrix.sync.aligned.m8n8.x4.shared.b16 {%0,%1,%2,%3}, [%4];"
                : "=r"(a0), "=r"(a1), "=r"(a2), "=r"(a3)
                : "r"(a_base + k0 * 2));
            #pragma unroll
            for (int nt = 0; nt < 8; nt++) {
                uint32_t w0, w1;
                asm volatile(
                    "ldmatrix.sync.aligned.m8n8.x2.shared.b16 {%0,%1}, [%2];"
                    : "=r"(w0), "=r"(w1)
                    : "r"(b_base + (nt * 8 * APAD + k0) * 2));
                asm volatile(
                    "mma.sync.aligned.m16n8k16.row.col.f32.f16.f16.f32 "
                    "{%0,%1,%2,%3}, {%4,%5,%6,%7}, {%8,%9}, {%0,%1,%2,%3};"
                    : "+f"(acc[nt][0]), "+f"(acc[nt][1]),
                      "+f"(acc[nt][2]), "+f"(acc[nt][3])
                    : "r"(a0), "r"(a1), "r"(a2), "r"(a3), "r"(w0), "r"(w1));
            }
        }
        __syncthreads();
    }

    // ---------------- h = relu(acc + b1) -> sA (fp16, [node][k]) ------------
    #pragma unroll
    for (int nt = 0; nt < 8; nt++) {
        int feat = nt * 8 + tig * 2;
        float bx = sb1[feat], by = sb1[feat + 1];
        int r0 = warp * 16 + grp;
        __half2 h01 = __floats2half2_rn(fmaxf(acc[nt][0] + bx, 0.f),
                                        fmaxf(acc[nt][1] + by, 0.f));
        __half2 h23 = __floats2half2_rn(fmaxf(acc[nt][2] + bx, 0.f),
                                        fmaxf(acc[nt][3] + by, 0.f));
        *reinterpret_cast<__half2*>(&sA[r0 * APAD + feat]) = h01;
        *reinterpret_cast<__half2*>(&sA[(r0 + 8) * APAD + feat]) = h23;
        acc[nt][0] = acc[nt][1] = acc[nt][2] = acc[nt][3] = 0.f;
    }
    // load stacked W2
    #pragma unroll
    for (int i = 0; i < 2; i++) {
        int idx = tid + i * 256;
        int j = idx >> 3, c = idx & 7;
        *reinterpret_cast<uint4*>(&sW[j * APAD + c * 8]) =
            reinterpret_cast<const uint4*>(g_w2h)[j * 8 + c];
    }
    __syncthreads();

    // ---------------- layer 2: K=64 -----------------------------------------
    #pragma unroll
    for (int k0 = 0; k0 < 64; k0 += 16) {
        uint32_t a0, a1, a2, a3;
        asm volatile(
            "ldmatrix.sync.aligned.m8n8.x4.shared.b16 {%0,%1,%2,%3}, [%4];"
            : "=r"(a0), "=r"(a1), "=r"(a2), "=r"(a3)
            : "r"(a_base + k0 * 2));
        #pragma unroll
        for (int nt = 0; nt < 8; nt++) {
            uint32_t w0, w1;
            asm volatile(
                "ldmatrix.sync.aligned.m8n8.x2.shared.b16 {%0,%1}, [%2];"
                : "=r"(w0), "=r"(w1)
                : "r"(b_base + (nt * 8 * APAD + k0) * 2));
            asm volatile(
                "mma.sync.aligned.m16n8k16.row.col.f32.f16.f16.f32 "
                "{%0,%1,%2,%3}, {%4,%5,%6,%7}, {%8,%9}, {%0,%1,%2,%3};"
                : "+f"(acc[nt][0]), "+f"(acc[nt][1]),
                  "+f"(acc[nt][2]), "+f"(acc[nt][3])
                : "r"(a0), "r"(a1), "r"(a2), "r"(a3), "r"(w0), "r"(w1));
        }
    }

    // ---------------- store: cols 0-31 -> g_p, 32-63 -> out (+b2) -----------
    #pragma unroll
    for (int nt = 0; nt < 8; nt++) {
        int col = nt * 8 + tig * 2;
        int r0 = node0 + warp * 16 + grp;
        int r1 = r0 + 8;
        if (col < 32) {
            if (r0 < N_NODES)
                reinterpret_cast<float2*>(g_p)[r0 * 16 + (col >> 1)] =
                    make_float2(acc[nt][0], acc[nt][1]);
            if (r1 < N_NODES)
                reinterpret_cast<float2*>(g_p)[r1 * 16 + (col >> 1)] =
                    make_float2(acc[nt][2], acc[nt][3]);
        } else {
            int cc = col - 32;
            float bx = sb2[cc], by = sb2[cc + 1];
            if (r0 < N_NODES)
                reinterpret_cast<float2*>(out)[r0 * 16 + (cc >> 1)] =
                    make_float2(acc[nt][0] + bx, acc[nt][1] + by);
            if (r1 < N_NODES)
                reinterpret_cast<float2*>(out)[r1 * 16 + (cc >> 1)] =
                    make_float2(acc[nt][2] + bx, acc[nt][3] + by);
        }
    }
}

// ---------------- K6: gather layer 2 (warp per node) -------------------------
__global__ __launch_bounds__(256) void gather32_kernel(float* __restrict__ out)
{
    int wid = threadIdx.x >> 5, lane = threadIdx.x & 31;
    int n = blockIdx.x * 8 + wid;
    if (n >= N_NODES) return;

    int start = g_rowptr[n], end = g_rowptr[n + 1];

    float a = 0.f;
    int e = start;
    for (; e + 4 <= end; e += 4) {
        int s0 = g_csr_src[e + 0];
        int s1 = g_csr_src[e + 1];
        int s2 = g_csr_src[e + 2];
        int s3 = g_csr_src[e + 3];
        float v0 = __ldg(&g_p[s0 * 32 + lane]);
        float v1 = __ldg(&g_p[s1 * 32 + lane]);
        float v2 = __ldg(&g_p[s2 * 32 + lane]);
        float v3 = __ldg(&g_p[s3 * 32 + lane]);
        a += (v0 + v1) + (v2 + v3);
    }
    for (; e < end; e++) {
        int s = g_csr_src[e];
        a += __ldg(&g_p[s * 32 + lane]);
    }
    float dinv = (end > start) ? 1.0f / (float)(end - start) : 0.0f;
    out[n * 32 + lane] += a * dinv;
}

// ---------------- launch ------------------------------------------------------
extern "C" void kernel_launch(void* const* d_in, const int* in_sizes, int n_in,
                              void* d_out, int out_size)
{
    const float* x    = (const float*)d_in[0];
    const int*   ei1  = (const int*)d_in[1];     // int32 (JAX x64 disabled)
    const int*   ei2  = (const int*)d_in[3];
    const float* W1l  = (const float*)d_in[5];
    const float* b1   = (const float*)d_in[6];
    const float* W1r  = (const float*)d_in[7];
    const float* W2l  = (const float*)d_in[8];
    const float* b2   = (const float*)d_in[9];
    const float* W2r  = (const float*)d_in[10];
    float*       out  = (float*)d_out;

    int E1 = in_sizes[1] / 2;
    int E2 = in_sizes[3] / 2;
    int E  = E1 + E2;

    // K0: x->fp16 || zero degrees || weights->fp16
    init_kernel<<<CONV_BLOCKS + DEG_BLOCKS + 1, 256>>>(
        reinterpret_cast<const float4*>(x), W1l, W1r, W2l, W2r);

    // CSR build
    count_deg_kernel<<<(E + 255) / 256, 256>>>(ei1, ei2, E1, E2);
    scan_block_kernel<<<NB_SCAN, 256>>>();
    scan_add_kernel<<<(N_NODES + 256) / 256, 256>>>(E);
    fill_csr_kernel<<<(E + 255) / 256, 256>>>(ei1, ei2, E1, E2);

    // layer-1 aggregation (gather, fp16)
    gather64_kernel<<<(N_NODES + 7) / 8, 256>>>();

    // fused two-layer GEMM on tensor cores -> g_p, out(self term)
    fused_mma_kernel<<<(N_NODES + 127) / 128, 256>>>(b1, b2, out);

    // layer-2 aggregation
    gather32_kernel<<<(N_NODES + 7) / 8, 256>>>(out);
}

// round 15
// speedup vs baseline: 1.8092x; 1.0445x over previous
#include <cuda_runtime.h>
#include <cuda_fp16.h>
#include <cuda_bf16.h>
#include <cstdint>

#define N_NODES 100000
#define MAX_E   1600000
#define NB_SCAN 98             // ceil(100000/1024)
#define APAD 72                // smem row stride in halves (144 B = 9*16B)

// ---------------- scratch (static device globals; no allocation) ------------
__device__ __align__(16) int     g_degi[N_NODES];        // zero at load; reset each run by scan_block
__device__ __align__(16) int     g_rowptr[N_NODES + 1];
__device__ __align__(16) int     g_fill[N_NODES];
__device__ __align__(16) int     g_blocksum[NB_SCAN + 1];
__device__ __align__(16) int     g_csr_src[MAX_E];
__device__ __align__(16) __half2 g_meanh[N_NODES * 32];  // fp16 neighbor mean
__device__ __align__(16) __half  g_w1lh[64 * 64];
__device__ __align__(16) __half  g_w1rh[64 * 64];
__device__ __align__(16) __half  g_w2h[64 * 64];         // rows 0-31 W2l, 32-63 W2r
__device__ __align__(16) float   g_p[N_NODES * 32];      // h @ W2l^T

__device__ __forceinline__ uint32_t smem_u32(const void* p) {
    return (uint32_t)__cvta_generic_to_shared(p);
}

// ---------------- K1: count in-degrees || weights->fp16 ----------------------
// Last block converts the weight matrices; others count degrees.
__global__ __launch_bounds__(256) void count_conv_kernel(
    const int* __restrict__ ei1, const int* __restrict__ ei2, int E1, int E2,
    const float* __restrict__ W1l, const float* __restrict__ W1r,
    const float* __restrict__ W2l, const float* __restrict__ W2r,
    int nEdgeBlocks)
{
    int bid = blockIdx.x;
    if (bid < nEdgeBlocks) {
        int t = bid * 256 + threadIdx.x;
        int E = E1 + E2;
        if (t >= E) return;
        int d = (t < E1) ? ei1[t + E1] : ei2[(t - E1) + E2];
        atomicAdd(&g_degi[d], 1);
    } else {
        int t = threadIdx.x;
        for (int i = t; i < 4096; i += 256) {
            g_w1lh[i] = __float2half_rn(W1l[i]);
            g_w1rh[i] = __float2half_rn(W1r[i]);
        }
        for (int i = t; i < 2048; i += 256) {
            g_w2h[i]        = __float2half_rn(W2l[i]);   // rows 0..31
            g_w2h[2048 + i] = __float2half_rn(W2r[i]);   // rows 32..63
        }
    }
}

// ---------------- K2a: per-block exclusive scan; resets degi for next run ---
__global__ __launch_bounds__(256) void scan_block_kernel()
{
    __shared__ int swarp[8];
    int tid = threadIdx.x, lane = tid & 31, wid = tid >> 5;
    int base = blockIdx.x * 1024 + tid * 4;

    int v0 = (base + 0 < N_NODES) ? g_degi[base + 0] : 0;
    int v1 = (base + 1 < N_NODES) ? g_degi[base + 1] : 0;
    int v2 = (base + 2 < N_NODES) ? g_degi[base + 2] : 0;
    int v3 = (base + 3 < N_NODES) ? g_degi[base + 3] : 0;
    int tsum = v0 + v1 + v2 + v3;

    // reset for next graph replay (count_conv assumes zeroed degi)
    if (base + 0 < N_NODES) g_degi[base + 0] = 0;
    if (base + 1 < N_NODES) g_degi[base + 1] = 0;
    if (base + 2 < N_NODES) g_degi[base + 2] = 0;
    if (base + 3 < N_NODES) g_degi[base + 3] = 0;

    int s = tsum;
    #pragma unroll
    for (int off = 1; off < 32; off <<= 1) {
        int t = __shfl_up_sync(0xffffffffu, s, off);
        if (lane >= off) s += t;
    }
    if (lane == 31) swarp[wid] = s;
    __syncthreads();
    if (tid == 0) {
        int r = 0;
        #pragma unroll
        for (int i = 0; i < 8; i++) { int t = swarp[i]; swarp[i] = r; r += t; }
        g_blocksum[blockIdx.x] = r;
    }
    __syncthreads();
    int excl = s - tsum + swarp[wid];
    if (base + 0 < N_NODES) g_rowptr[base + 0] = excl;
    if (base + 1 < N_NODES) g_rowptr[base + 1] = excl + v0;
    if (base + 2 < N_NODES) g_rowptr[base + 2] = excl + v0 + v1;
    if (base + 3 < N_NODES) g_rowptr[base + 3] = excl + v0 + v1 + v2;
}

// ---------------- K2b: add block offsets (warp-parallel sum) ----------------
__global__ __launch_bounds__(256) void scan_add_kernel(int E)
{
    __shared__ int soff;
    int t = blockIdx.x * blockDim.x + threadIdx.x;
    int chunk = (blockIdx.x * 256) >> 10;           // uniform per block
    if (threadIdx.x < 32) {
        int r = 0;
        for (int i = threadIdx.x; i < chunk; i += 32) r += g_blocksum[i];
        #pragma unroll
        for (int off = 16; off > 0; off >>= 1)
            r += __shfl_down_sync(0xffffffffu, r, off);
        if (threadIdx.x == 0) soff = r;
    }
    __syncthreads();
    if (t < N_NODES) {
        int val = g_rowptr[t] + soff;
        g_rowptr[t] = val;
        g_fill[t] = val;
    }
    if (t == N_NODES) g_rowptr[N_NODES] = E;
}

// ---------------- K3: fill CSR slots -----------------------------------------
__global__ __launch_bounds__(256) void fill_csr_kernel(
    const int* __restrict__ ei1, const int* __restrict__ ei2, int E1, int E2)
{
    int t = blockIdx.x * blockDim.x + threadIdx.x;
    int E = E1 + E2;
    if (t >= E) return;
    int s, d;
    if (t < E1) { s = ei1[t];      d = ei1[t + E1]; }
    else        { int u = t - E1;  s = ei2[u];  d = ei2[u + E2]; }
    int pos = atomicAdd(&g_fill[d], 1);
    g_csr_src[pos] = s;
}

// ---------------- K4: gather layer 1 (warp/node, coalesced idx + shfl) ------
__global__ __launch_bounds__(256) void gather64_kernel(const float* __restrict__ x)
{
    int wid = threadIdx.x >> 5, lane = threadIdx.x & 31;
    int n = blockIdx.x * 8 + wid;
    if (n >= N_NODES) return;                 // warp-uniform

    int start = g_rowptr[n], end = g_rowptr[n + 1];
    const float2* x2 = reinterpret_cast<const float2*>(x);

    float ax = 0.f, ay = 0.f;
    for (int base = start; base < end; base += 32) {
        int t = base + lane;
        int sidx = (t < end) ? g_csr_src[t] : 0;   // one coalesced load / 32 edges
        int m = end - base; if (m > 32) m = 32;
        int j = 0;
        for (; j + 4 <= m; j += 4) {
            int s0 = __shfl_sync(0xffffffffu, sidx, j + 0);
            int s1 = __shfl_sync(0xffffffffu, sidx, j + 1);
            int s2 = __shfl_sync(0xffffffffu, sidx, j + 2);
            int s3 = __shfl_sync(0xffffffffu, sidx, j + 3);
            float2 v0 = __ldg(&x2[s0 * 32 + lane]);
            float2 v1 = __ldg(&x2[s1 * 32 + lane]);
            float2 v2 = __ldg(&x2[s2 * 32 + lane]);
            float2 v3 = __ldg(&x2[s3 * 32 + lane]);
            ax += (v0.x + v1.x) + (v2.x + v3.x);
            ay += (v0.y + v1.y) + (v2.y + v3.y);
        }
        for (; j < m; j++) {
            int s0 = __shfl_sync(0xffffffffu, sidx, j);
            float2 v = __ldg(&x2[s0 * 32 + lane]);
            ax += v.x; ay += v.y;
        }
    }
    float dinv = (end > start) ? 1.0f / (float)(end - start) : 0.0f;
    g_meanh[n * 32 + lane] = __floats2half2_rn(ax * dinv, ay * dinv);
}

// ---------------- K5: fused two-layer GEMM on tensor cores (HMMA) -----------
// Block: 128 nodes x 64 outs, 8 warps. x converted fp32->fp16 inline at staging.
__global__ __launch_bounds__(256) void fused_mma_kernel(
    const float4* __restrict__ x4,
    const float* __restrict__ b1, const float* __restrict__ b2,
    float* __restrict__ out)
{
    __shared__ __half sA[128 * APAD];   // operand / h tile (18432 B)
    __shared__ __half sW[64 * APAD];    // weight tile (9216 B)
    __shared__ float  sb1[64];
    __shared__ float  sb2[32];

    int tid = threadIdx.x;
    int warp = tid >> 5, lane = tid & 31;
    int grp = lane >> 2, tig = lane & 3;
    int node0 = blockIdx.x * 128;

    if (tid < 64) sb1[tid] = b1[tid];
    if (tid >= 64 && tid < 96) sb2[tid - 64] = b2[tid - 64];

    int a_row  = lane & 15;
    int a_koff = (lane >> 4) * 8;
    int b_row  = lane & 7;
    int b_koff = ((lane >> 3) & 1) * 8;

    uint32_t a_base = smem_u32(&sA[(warp * 16 + a_row) * APAD + a_koff]);
    uint32_t b_base = smem_u32(&sW[b_row * APAD + b_koff]);

    float acc[8][4] = {};

    // ---------------- layer 1: two K=64 stages ------------------------------
    #pragma unroll
    for (int stage = 0; stage < 2; stage++) {
        const uint4* Wsrc = reinterpret_cast<const uint4*>(stage ? g_w1rh : g_w1lh);
        #pragma unroll
        for (int i = 0; i < 4; i++) {                  // A: 128 rows x 8 uint4
            int idx = tid + i * 256;
            int n = idx >> 3, c = idx & 7;
            int gn = node0 + n;
            uint4 v;
            if (stage == 0) {
                v = (gn < N_NODES)
                    ? reinterpret_cast<const uint4*>(g_meanh)[gn * 8 + c]
                    : make_uint4(0, 0, 0, 0);
            } else {
                float4 va, vb;
                if (gn < N_NODES) {
                    va = x4[gn * 16 + c * 2];
                    vb = x4[gn * 16 + c * 2 + 1];
                } else {
                    va = make_float4(0.f, 0.f, 0.f, 0.f);
                    vb = va;
                }
                __half2 h0 = __floats2half2_rn(va.x, va.y);
                __half2 h1 = __floats2half2_rn(va.z, va.w);
                __half2 h2 = __floats2half2_rn(vb.x, vb.y);
                __half2 h3 = __floats2half2_rn(vb.z, vb.w);
                v.x = *reinterpret_cast<uint32_t*>(&h0);
                v.y = *reinterpret_cast<uint32_t*>(&h1);
                v.z = *reinterpret_cast<uint32_t*>(&h2);
                v.w = *reinterpret_cast<uint32_t*>(&h3);
            }
            *reinterpret_cast<uint4*>(&sA[n * APAD + c * 8]) = v;
        }
        #pragma unroll
        for (int i = 0; i < 2; i++) {                  // W: 64 rows x 8 uint4
            int idx = tid + i * 256;
            int j = idx >> 3, c = idx & 7;
            *reinterpret_cast<uint4*>(&sW[j * APAD + c * 8]) = Wsrc[j * 8 + c];
        }
        __syncthreads();

        #pragma unroll
        for (int k0 = 0; k0 < 64; k0 += 16) {
            uint32_t a0, a1, a2, a3;
            asm volatile(
                "ldmatrix.sync.aligned.m8n8.x4.shared.b16 {%0,%1,%2,%3}, [%4];"
                : "=r"(a0), "=r"(a1), "=r"(a2), "=r"(a3)
                : "r"(a_base + k0 * 2));
            #pragma unroll
            for (int nt = 0; nt < 8; nt++) {
                uint32_t w0, w1;
                asm volatile(
                    "ldmatrix.sync.aligned.m8n8.x2.shared.b16 {%0,%1}, [%2];"
                    : "=r"(w0), "=r"(w1)
                    : "r"(b_base + (nt * 8 * APAD + k0) * 2));
                asm volatile(
                    "mma.sync.aligned.m16n8k16.row.col.f32.f16.f16.f32 "
                    "{%0,%1,%2,%3}, {%4,%5,%6,%7}, {%8,%9}, {%0,%1,%2,%3};"
                    : "+f"(acc[nt][0]), "+f"(acc[nt][1]),
                      "+f"(acc[nt][2]), "+f"(acc[nt][3])
                    : "r"(a0), "r"(a1), "r"(a2), "r"(a3), "r"(w0), "r"(w1));
            }
        }
        __syncthreads();
    }

    // ---------------- h = relu(acc + b1) -> sA (fp16, [node][k]) ------------
    #pragma unroll
    for (int nt = 0; nt < 8; nt++) {
        int feat = nt * 8 + tig * 2;
        float bx = sb1[feat], by = sb1[feat + 1];
        int r0 = warp * 16 + grp;
        __half2 h01 = __floats2half2_rn(fmaxf(acc[nt][0] + bx, 0.f),
                                        fmaxf(acc[nt][1] + by, 0.f));
        __half2 h23 = __floats2half2_rn(fmaxf(acc[nt][2] + bx, 0.f),
                                        fmaxf(acc[nt][3] + by, 0.f));
        *reinterpret_cast<__half2*>(&sA[r0 * APAD + feat]) = h01;
        *reinterpret_cast<__half2*>(&sA[(r0 + 8) * APAD + feat]) = h23;
        acc[nt][0] = acc[nt][1] = acc[nt][2] = acc[nt][3] = 0.f;
    }
    // load stacked W2
    #pragma unroll
    for (int i = 0; i < 2; i++) {
        int idx = tid + i * 256;
        int j = idx >> 3, c = idx & 7;
        *reinterpret_cast<uint4*>(&sW[j * APAD + c * 8]) =
            reinterpret_cast<const uint4*>(g_w2h)[j * 8 + c];
    }
    __syncthreads();

    // ---------------- layer 2: K=64 -----------------------------------------
    #pragma unroll
    for (int k0 = 0; k0 < 64; k0 += 16) {
        uint32_t a0, a1, a2, a3;
        asm volatile(
            "ldmatrix.sync.aligned.m8n8.x4.shared.b16 {%0,%1,%2,%3}, [%4];"
            : "=r"(a0), "=r"(a1), "=r"(a2), "=r"(a3)
            : "r"(a_base + k0 * 2));
        #pragma unroll
        for (int nt = 0; nt < 8; nt++) {
            uint32_t w0, w1;
            asm volatile(
                "ldmatrix.sync.aligned.m8n8.x2.shared.b16 {%0,%1}, [%2];"
                : "=r"(w0), "=r"(w1)
                : "r"(b_base + (nt * 8 * APAD + k0) * 2));
            asm volatile(
                "mma.sync.aligned.m16n8k16.row.col.f32.f16.f16.f32 "
                "{%0,%1,%2,%3}, {%4,%5,%6,%7}, {%8,%9}, {%0,%1,%2,%3};"
                : "+f"(acc[nt][0]), "+f"(acc[nt][1]),
                  "+f"(acc[nt][2]), "+f"(acc[nt][3])
                : "r"(a0), "r"(a1), "r"(a2), "r"(a3), "r"(w0), "r"(w1));
        }
    }

    // ---------------- store: cols 0-31 -> g_p, 32-63 -> out (+b2) -----------
    #pragma unroll
    for (int nt = 0; nt < 8; nt++) {
        int col = nt * 8 + tig * 2;
        int r0 = node0 + warp * 16 + grp;
        int r1 = r0 + 8;
        if (col < 32) {
            if (r0 < N_NODES)
                reinterpret_cast<float2*>(g_p)[r0 * 16 + (col >> 1)] =
                    make_float2(acc[nt][0], acc[nt][1]);
            if (r1 < N_NODES)
                reinterpret_cast<float2*>(g_p)[r1 * 16 + (col >> 1)] =
                    make_float2(acc[nt][2], acc[nt][3]);
        } else {
            int cc = col - 32;
            float bx = sb2[cc], by = sb2[cc + 1];
            if (r0 < N_NODES)
                reinterpret_cast<float2*>(out)[r0 * 16 + (cc >> 1)] =
                    make_float2(acc[nt][0] + bx, acc[nt][1] + by);
            if (r1 < N_NODES)
                reinterpret_cast<float2*>(out)[r1 * 16 + (cc >> 1)] =
                    make_float2(acc[nt][2] + bx, acc[nt][3] + by);
        }
    }
}

// ---------------- K6: gather layer 2 (warp/node, coalesced idx + shfl) ------
__global__ __launch_bounds__(256) void gather32_kernel(float* __restrict__ out)
{
    int wid = threadIdx.x >> 5, lane = threadIdx.x & 31;
    int n = blockIdx.x * 8 + wid;
    if (n >= N_NODES) return;                 // warp-uniform

    int start = g_rowptr[n], end = g_rowptr[n + 1];

    float a = 0.f;
    for (int base = start; base < end; base += 32) {
        int t = base + lane;
        int sidx = (t < end) ? g_csr_src[t] : 0;
        int m = end - base; if (m > 32) m = 32;
        int j = 0;
        for (; j + 4 <= m; j += 4) {
            int s0 = __shfl_sync(0xffffffffu, sidx, j + 0);
            int s1 = __shfl_sync(0xffffffffu, sidx, j + 1);
            int s2 = __shfl_sync(0xffffffffu, sidx, j + 2);
            int s3 = __shfl_sync(0xffffffffu, sidx, j + 3);
            float v0 = __ldg(&g_p[s0 * 32 + lane]);
            float v1 = __ldg(&g_p[s1 * 32 + lane]);
            float v2 = __ldg(&g_p[s2 * 32 + lane]);
            float v3 = __ldg(&g_p[s3 * 32 + lane]);
            a += (v0 + v1) + (v2 + v3);
        }
        for (; j < m; j++) {
            int s0 = __shfl_sync(0xffffffffu, sidx, j);
            a += __ldg(&g_p[s0 * 32 + lane]);
        }
    }
    float dinv = (end > start) ? 1.0f / (float)(end - start) : 0.0f;
    out[n * 32 + lane] += a * dinv;
}

// ---------------- launch ------------------------------------------------------
extern "C" void kernel_launch(void* const* d_in, const int* in_sizes, int n_in,
                              void* d_out, int out_size)
{
    const float* x    = (const float*)d_in[0];
    const int*   ei1  = (const int*)d_in[1];     // int32 (JAX x64 disabled)
    const int*   ei2  = (const int*)d_in[3];
    const float* W1l  = (const float*)d_in[5];
    const float* b1   = (const float*)d_in[6];
    const float* W1r  = (const float*)d_in[7];
    const float* W2l  = (const float*)d_in[8];
    const float* b2   = (const float*)d_in[9];
    const float* W2r  = (const float*)d_in[10];
    float*       out  = (float*)d_out;

    int E1 = in_sizes[1] / 2;
    int E2 = in_sizes[3] / 2;
    int E  = E1 + E2;
    int nEdgeBlocks = (E + 255) / 256;

    // K1: degree count || weight fp16 conversion (degi zeroed by prior run)
    count_conv_kernel<<<nEdgeBlocks + 1, 256>>>(
        ei1, ei2, E1, E2, W1l, W1r, W2l, W2r, nEdgeBlocks);

    // CSR build
    scan_block_kernel<<<NB_SCAN, 256>>>();
    scan_add_kernel<<<(N_NODES + 256) / 256, 256>>>(E);
    fill_csr_kernel<<<nEdgeBlocks, 256>>>(ei1, ei2, E1, E2);

    // layer-1 aggregation (fp32 x, fp16 mean out)
    gather64_kernel<<<(N_NODES + 7) / 8, 256>>>(x);

    // fused two-layer GEMM on tensor cores -> g_p, out(self term)
    fused_mma_kernel<<<(N_NODES + 127) / 128, 256>>>(
        reinterpret_cast<const float4*>(x), b1, b2, out);

    // layer-2 aggregation
    gather32_kernel<<<(N_NODES + 7) / 8, 256>>>(out);
}

// round 16
// speedup vs baseline: 1.8659x; 1.0313x over previous
#include <cuda_runtime.h>
#include <cuda_fp16.h>
#include <cuda_bf16.h>
#include <cstdint>

#define N_NODES 100000
#define MAX_E   1600000
#define NB_SCAN 98             // ceil(100000/1024)
#define XCONV_BLOCKS 3125      // 800k threads, 8 floats each = 1.6M float4
#define APAD 72                // smem row stride in halves (144 B = 9*16B)

// ---------------- scratch (static device globals; no allocation) ------------
__device__ __align__(16) int     g_degi[N_NODES];        // zeroed by scan kernel each run
__device__ __align__(16) int     g_rowptr[N_NODES + 1];
__device__ __align__(16) int     g_fill[N_NODES];
__device__ __align__(16) int     g_blocksum[NB_SCAN + 1];
__device__ int                   g_arrive;               // scan rendezvous (0 at entry/exit)
__device__ int                   g_depart;
__device__ __align__(16) int     g_csr_src[MAX_E];
__device__ __align__(16) __half2 g_xh[N_NODES * 32];     // fp16 copy of x
__device__ __align__(16) __half2 g_meanh[N_NODES * 32];  // fp16 neighbor mean
__device__ __align__(16) __half  g_w1lh[64 * 64];
__device__ __align__(16) __half  g_w1rh[64 * 64];
__device__ __align__(16) __half  g_w2h[64 * 64];         // rows 0-31 W2l, 32-63 W2r
__device__ __align__(16) __half  g_ph[N_NODES * 32];     // h @ W2l^T (fp16)

__device__ __forceinline__ uint32_t smem_u32(const void* p) {
    return (uint32_t)__cvta_generic_to_shared(p);
}

// ---------------- K1: degree count || weights->fp16 || x->fp16 --------------
__global__ __launch_bounds__(256) void count_conv_kernel(
    const int* __restrict__ ei1, const int* __restrict__ ei2, int E1, int E2,
    const float* __restrict__ W1l, const float* __restrict__ W1r,
    const float* __restrict__ W2l, const float* __restrict__ W2r,
    const float4* __restrict__ x4, int nEdgeBlocks)
{
    int bid = blockIdx.x;
    if (bid < nEdgeBlocks) {
        int t = bid * 256 + threadIdx.x;
        int E = E1 + E2;
        if (t >= E) return;
        int d = (t < E1) ? ei1[t + E1] : ei2[(t - E1) + E2];
        atomicAdd(&g_degi[d], 1);
    } else if (bid == nEdgeBlocks) {
        int t = threadIdx.x;
        for (int i = t; i < 4096; i += 256) {
            g_w1lh[i] = __float2half_rn(W1l[i]);
            g_w1rh[i] = __float2half_rn(W1r[i]);
        }
        for (int i = t; i < 2048; i += 256) {
            g_w2h[i]        = __float2half_rn(W2l[i]);   // rows 0..31
            g_w2h[2048 + i] = __float2half_rn(W2r[i]);   // rows 32..63
        }
    } else {
        int t = (bid - nEdgeBlocks - 1) * 256 + threadIdx.x;   // < 800000
        float4 va = x4[2 * t], vb = x4[2 * t + 1];
        __half2 h0 = __floats2half2_rn(va.x, va.y);
        __half2 h1 = __floats2half2_rn(va.z, va.w);
        __half2 h2 = __floats2half2_rn(vb.x, vb.y);
        __half2 h3 = __floats2half2_rn(vb.z, vb.w);
        uint4 v;
        v.x = *reinterpret_cast<uint32_t*>(&h0);
        v.y = *reinterpret_cast<uint32_t*>(&h1);
        v.z = *reinterpret_cast<uint32_t*>(&h2);
        v.w = *reinterpret_cast<uint32_t*>(&h3);
        reinterpret_cast<uint4*>(g_xh)[t] = v;
    }
}

// ---------------- K2: fused exclusive scan (single launch, 98 blocks) -------
// 98 blocks <= 148 SMs -> all co-resident; arrive/depart counters return to 0.
__global__ __launch_bounds__(256) void scan_fused_kernel(int E)
{
    __shared__ int swarp[8];
    __shared__ int soff;
    int tid = threadIdx.x, lane = tid & 31, wid = tid >> 5;
    int bid = blockIdx.x;
    int base = bid * 1024 + tid * 4;

    int v0 = (base + 0 < N_NODES) ? g_degi[base + 0] : 0;
    int v1 = (base + 1 < N_NODES) ? g_degi[base + 1] : 0;
    int v2 = (base + 2 < N_NODES) ? g_degi[base + 2] : 0;
    int v3 = (base + 3 < N_NODES) ? g_degi[base + 3] : 0;
    int tsum = v0 + v1 + v2 + v3;

    // reset degi for the next replay (count_conv assumes zeroed)
    if (base + 0 < N_NODES) g_degi[base + 0] = 0;
    if (base + 1 < N_NODES) g_degi[base + 1] = 0;
    if (base + 2 < N_NODES) g_degi[base + 2] = 0;
    if (base + 3 < N_NODES) g_degi[base + 3] = 0;

    int s = tsum;
    #pragma unroll
    for (int off = 1; off < 32; off <<= 1) {
        int t = __shfl_up_sync(0xffffffffu, s, off);
        if (lane >= off) s += t;
    }
    if (lane == 31) swarp[wid] = s;
    __syncthreads();
    if (tid == 0) {
        int r = 0;
        #pragma unroll
        for (int i = 0; i < 8; i++) { int t = swarp[i]; swarp[i] = r; r += t; }
        g_blocksum[bid] = r;
        __threadfence();
        atomicAdd(&g_arrive, 1);
        while (atomicAdd(&g_arrive, 0) < NB_SCAN) { }   // rendezvous
    }
    __syncthreads();

    // chunk offset = sum of blocksum[0..bid)
    if (tid < 32) {
        int r = 0;
        for (int i = tid; i < bid; i += 32) r += g_blocksum[i];
        #pragma unroll
        for (int off = 16; off > 0; off >>= 1)
            r += __shfl_down_sync(0xffffffffu, r, off);
        if (tid == 0) soff = r;
    }
    __syncthreads();

    int excl = s - tsum + swarp[wid] + soff;
    if (base + 0 < N_NODES) { g_rowptr[base + 0] = excl;               g_fill[base + 0] = excl; }
    if (base + 1 < N_NODES) { g_rowptr[base + 1] = excl + v0;          g_fill[base + 1] = excl + v0; }
    if (base + 2 < N_NODES) { g_rowptr[base + 2] = excl + v0 + v1;     g_fill[base + 2] = excl + v0 + v1; }
    if (base + 3 < N_NODES) { g_rowptr[base + 3] = excl + v0 + v1 + v2; g_fill[base + 3] = excl + v0 + v1 + v2; }
    if (tid == 0 && bid == NB_SCAN - 1) g_rowptr[N_NODES] = E;

    // depart: last block resets the counters to 0 for the next replay
    __syncthreads();
    if (tid == 0) {
        int d = atomicAdd(&g_depart, 1);
        if (d == NB_SCAN - 1) { g_arrive = 0; g_depart = 0; }
    }
}

// ---------------- K3: fill CSR slots -----------------------------------------
__global__ __launch_bounds__(256) void fill_csr_kernel(
    const int* __restrict__ ei1, const int* __restrict__ ei2, int E1, int E2)
{
    int t = blockIdx.x * blockDim.x + threadIdx.x;
    int E = E1 + E2;
    if (t >= E) return;
    int s, d;
    if (t < E1) { s = ei1[t];      d = ei1[t + E1]; }
    else        { int u = t - E1;  s = ei2[u];  d = ei2[u + E2]; }
    int pos = atomicAdd(&g_fill[d], 1);
    g_csr_src[pos] = s;
}

// ---------------- K4: gather layer 1 (warp/node, fp16 rows) ------------------
__global__ __launch_bounds__(256) void gather64_kernel()
{
    int wid = threadIdx.x >> 5, lane = threadIdx.x & 31;
    int n = blockIdx.x * 8 + wid;
    if (n >= N_NODES) return;                 // warp-uniform

    int start = g_rowptr[n], end = g_rowptr[n + 1];

    float ax = 0.f, ay = 0.f;
    for (int base = start; base < end; base += 32) {
        int t = base + lane;
        int sidx = (t < end) ? g_csr_src[t] : 0;   // one coalesced load / 32 edges
        int m = end - base; if (m > 32) m = 32;
        int j = 0;
        for (; j + 4 <= m; j += 4) {
            int s0 = __shfl_sync(0xffffffffu, sidx, j + 0);
            int s1 = __shfl_sync(0xffffffffu, sidx, j + 1);
            int s2 = __shfl_sync(0xffffffffu, sidx, j + 2);
            int s3 = __shfl_sync(0xffffffffu, sidx, j + 3);
            float2 v0 = __half22float2(g_xh[s0 * 32 + lane]);
            float2 v1 = __half22float2(g_xh[s1 * 32 + lane]);
            float2 v2 = __half22float2(g_xh[s2 * 32 + lane]);
            float2 v3 = __half22float2(g_xh[s3 * 32 + lane]);
            ax += (v0.x + v1.x) + (v2.x + v3.x);
            ay += (v0.y + v1.y) + (v2.y + v3.y);
        }
        for (; j < m; j++) {
            int s0 = __shfl_sync(0xffffffffu, sidx, j);
            float2 v = __half22float2(g_xh[s0 * 32 + lane]);
            ax += v.x; ay += v.y;
        }
    }
    float dinv = (end > start) ? 1.0f / (float)(end - start) : 0.0f;
    g_meanh[n * 32 + lane] = __floats2half2_rn(ax * dinv, ay * dinv);
}

// ---------------- K5: fused two-layer GEMM on tensor cores (HMMA) -----------
__global__ __launch_bounds__(256) void fused_mma_kernel(
    const float* __restrict__ b1, const float* __restrict__ b2,
    float* __restrict__ out)
{
    __shared__ __half sA[128 * APAD];   // operand / h tile (18432 B)
    __shared__ __half sW[64 * APAD];    // weight tile (9216 B)
    __shared__ float  sb1[64];
    __shared__ float  sb2[32];

    int tid = threadIdx.x;
    int warp = tid >> 5, lane = tid & 31;
    int grp = lane >> 2, tig = lane & 3;
    int node0 = blockIdx.x * 128;

    if (tid < 64) sb1[tid] = b1[tid];
    if (tid >= 64 && tid < 96) sb2[tid - 64] = b2[tid - 64];

    int a_row  = lane & 15;
    int a_koff = (lane >> 4) * 8;
    int b_row  = lane & 7;
    int b_koff = ((lane >> 3) & 1) * 8;

    uint32_t a_base = smem_u32(&sA[(warp * 16 + a_row) * APAD + a_koff]);
    uint32_t b_base = smem_u32(&sW[b_row * APAD + b_koff]);

    float acc[8][4] = {};

    // ---------------- layer 1: two K=64 stages ------------------------------
    #pragma unroll
    for (int stage = 0; stage < 2; stage++) {
        const uint4* Asrc = reinterpret_cast<const uint4*>(stage ? g_xh : g_meanh);
        const uint4* Wsrc = reinterpret_cast<const uint4*>(stage ? g_w1rh : g_w1lh);
        #pragma unroll
        for (int i = 0; i < 4; i++) {                  // A: 128 rows x 8 uint4
            int idx = tid + i * 256;
            int n = idx >> 3, c = idx & 7;
            int gn = node0 + n;
            uint4 v = (gn < N_NODES) ? Asrc[gn * 8 + c] : make_uint4(0, 0, 0, 0);
            *reinterpret_cast<uint4*>(&sA[n * APAD + c * 8]) = v;
        }
        #pragma unroll
        for (int i = 0; i < 2; i++) {                  // W: 64 rows x 8 uint4
            int idx = tid + i * 256;
            int j = idx >> 3, c = idx & 7;
            *reinterpret_cast<uint4*>(&sW[j * APAD + c * 8]) = Wsrc[j * 8 + c];
        }
        __syncthreads();

        #pragma unroll
        for (int k0 = 0; k0 < 64; k0 += 16) {
            uint32_t a0, a1, a2, a3;
            asm volatile(
                "ldmatrix.sync.aligned.m8n8.x4.shared.b16 {%0,%1,%2,%3}, [%4];"
                : "=r"(a0), "=r"(a1), "=r"(a2), "=r"(a3)
                : "r"(a_base + k0 * 2));
            #pragma unroll
            for (int nt = 0; nt < 8; nt++) {
                uint32_t w0, w1;
                asm volatile(
                    "ldmatrix.sync.aligned.m8n8.x2.shared.b16 {%0,%1}, [%2];"
                    : "=r"(w0), "=r"(w1)
                    : "r"(b_base + (nt * 8 * APAD + k0) * 2));
                asm volatile(
                    "mma.sync.aligned.m16n8k16.row.col.f32.f16.f16.f32 "
                    "{%0,%1,%2,%3}, {%4,%5,%6,%7}, {%8,%9}, {%0,%1,%2,%3};"
                    : "+f"(acc[nt][0]), "+f"(acc[nt][1]),
                      "+f"(acc[nt][2]), "+f"(acc[nt][3])
                    : "r"(a0), "r"(a1), "r"(a2), "r"(a3), "r"(w0), "r"(w1));
            }
        }
        __syncthreads();
    }

    // ---------------- h = relu(acc + b1) -> sA (fp16, [node][k]) ------------
    #pragma unroll
    for (int nt = 0; nt < 8; nt++) {
        int feat = nt * 8 + tig * 2;
        float bx = sb1[feat], by = sb1[feat + 1];
        int r0 = warp * 16 + grp;
        __half2 h01 = __floats2half2_rn(fmaxf(acc[nt][0] + bx, 0.f),
                                        fmaxf(acc[nt][1] + by, 0.f));
        __half2 h23 = __floats2half2_rn(fmaxf(acc[nt][2] + bx, 0.f),
                                        fmaxf(acc[nt][3] + by, 0.f));
        *reinterpret_cast<__half2*>(&sA[r0 * APAD + feat]) = h01;
        *reinterpret_cast<__half2*>(&sA[(r0 + 8) * APAD + feat]) = h23;
        acc[nt][0] = acc[nt][1] = acc[nt][2] = acc[nt][3] = 0.f;
    }
    // load stacked W2
    #pragma unroll
    for (int i = 0; i < 2; i++) {
        int idx = tid + i * 256;
        int j = idx >> 3, c = idx & 7;
        *reinterpret_cast<uint4*>(&sW[j * APAD + c * 8]) =
            reinterpret_cast<const uint4*>(g_w2h)[j * 8 + c];
    }
    __syncthreads();

    // ---------------- layer 2: K=64 -----------------------------------------
    #pragma unroll
    for (int k0 = 0; k0 < 64; k0 += 16) {
        uint32_t a0, a1, a2, a3;
        asm volatile(
            "ldmatrix.sync.aligned.m8n8.x4.shared.b16 {%0,%1,%2,%3}, [%4];"
            : "=r"(a0), "=r"(a1), "=r"(a2), "=r"(a3)
            : "r"(a_base + k0 * 2));
        #pragma unroll
        for (int nt = 0; nt < 8; nt++) {
            uint32_t w0, w1;
            asm volatile(
                "ldmatrix.sync.aligned.m8n8.x2.shared.b16 {%0,%1}, [%2];"
                : "=r"(w0), "=r"(w1)
                : "r"(b_base + (nt * 8 * APAD + k0) * 2));
            asm volatile(
                "mma.sync.aligned.m16n8k16.row.col.f32.f16.f16.f32 "
                "{%0,%1,%2,%3}, {%4,%5,%6,%7}, {%8,%9}, {%0,%1,%2,%3};"
                : "+f"(acc[nt][0]), "+f"(acc[nt][1]),
                  "+f"(acc[nt][2]), "+f"(acc[nt][3])
                : "r"(a0), "r"(a1), "r"(a2), "r"(a3), "r"(w0), "r"(w1));
        }
    }

    // ------- store: cols 0-31 -> g_ph (fp16), 32-63 -> out (fp32 + b2) ------
    #pragma unroll
    for (int nt = 0; nt < 8; nt++) {
        int col = nt * 8 + tig * 2;
        int r0 = node0 + warp * 16 + grp;
        int r1 = r0 + 8;
        if (col < 32) {
            if (r0 < N_NODES)
                reinterpret_cast<__half2*>(g_ph)[r0 * 16 + (col >> 1)] =
                    __floats2half2_rn(acc[nt][0], acc[nt][1]);
            if (r1 < N_NODES)
                reinterpret_cast<__half2*>(g_ph)[r1 * 16 + (col >> 1)] =
                    __floats2half2_rn(acc[nt][2], acc[nt][3]);
        } else {
            int cc = col - 32;
            float bx = sb2[cc], by = sb2[cc + 1];
            if (r0 < N_NODES)
                reinterpret_cast<float2*>(out)[r0 * 16 + (cc >> 1)] =
                    make_float2(acc[nt][0] + bx, acc[nt][1] + by);
            if (r1 < N_NODES)
                reinterpret_cast<float2*>(out)[r1 * 16 + (cc >> 1)] =
                    make_float2(acc[nt][2] + bx, acc[nt][3] + by);
        }
    }
}

// ---------------- K6: gather layer 2 (warp/node, fp16 rows) ------------------
__global__ __launch_bounds__(256) void gather32_kernel(float* __restrict__ out)
{
    int wid = threadIdx.x >> 5, lane = threadIdx.x & 31;
    int n = blockIdx.x * 8 + wid;
    if (n >= N_NODES) return;                 // warp-uniform

    int start = g_rowptr[n], end = g_rowptr[n + 1];

    float a = 0.f;
    for (int base = start; base < end; base += 32) {
        int t = base + lane;
        int sidx = (t < end) ? g_csr_src[t] : 0;
        int m = end - base; if (m > 32) m = 32;
        int j = 0;
        for (; j + 4 <= m; j += 4) {
            int s0 = __shfl_sync(0xffffffffu, sidx, j + 0);
            int s1 = __shfl_sync(0xffffffffu, sidx, j + 1);
            int s2 = __shfl_sync(0xffffffffu, sidx, j + 2);
            int s3 = __shfl_sync(0xffffffffu, sidx, j + 3);
            float v0 = __half2float(g_ph[s0 * 32 + lane]);
            float v1 = __half2float(g_ph[s1 * 32 + lane]);
            float v2 = __half2float(g_ph[s2 * 32 + lane]);
            float v3 = __half2float(g_ph[s3 * 32 + lane]);
            a += (v0 + v1) + (v2 + v3);
        }
        for (; j < m; j++) {
            int s0 = __shfl_sync(0xffffffffu, sidx, j);
            a += __half2float(g_ph[s0 * 32 + lane]);
        }
    }
    float dinv = (end > start) ? 1.0f / (float)(end - start) : 0.0f;
    out[n * 32 + lane] += a * dinv;
}

// ---------------- launch ------------------------------------------------------
extern "C" void kernel_launch(void* const* d_in, const int* in_sizes, int n_in,
                              void* d_out, int out_size)
{
    const float* x    = (const float*)d_in[0];
    const int*   ei1  = (const int*)d_in[1];     // int32 (JAX x64 disabled)
    const int*   ei2  = (const int*)d_in[3];
    const float* W1l  = (const float*)d_in[5];
    const float* b1   = (const float*)d_in[6];
    const float* W1r  = (const float*)d_in[7];
    const float* W2l  = (const float*)d_in[8];
    const float* b2   = (const float*)d_in[9];
    const float* W2r  = (const float*)d_in[10];
    float*       out  = (float*)d_out;

    int E1 = in_sizes[1] / 2;
    int E2 = in_sizes[3] / 2;
    int E  = E1 + E2;
    int nEdgeBlocks = (E + 255) / 256;

    // K1: degree count || weight fp16 conversion || x fp16 conversion
    count_conv_kernel<<<nEdgeBlocks + 1 + XCONV_BLOCKS, 256>>>(
        ei1, ei2, E1, E2, W1l, W1r, W2l, W2r,
        reinterpret_cast<const float4*>(x), nEdgeBlocks);

    // K2: fused scan (single launch)
    scan_fused_kernel<<<NB_SCAN, 256>>>(E);

    // K3: fill CSR
    fill_csr_kernel<<<nEdgeBlocks, 256>>>(ei1, ei2, E1, E2);

    // K4: layer-1 aggregation (fp16 rows)
    gather64_kernel<<<(N_NODES + 7) / 8, 256>>>();

    // K5: fused two-layer GEMM on tensor cores -> g_ph, out(self term)
    fused_mma_kernel<<<(N_NODES + 127) / 128, 256>>>(b1, b2, out);

    // K6: layer-2 aggregation (fp16 rows)
    gather32_kernel<<<(N_NODES + 7) / 8, 256>>>(out);
}

// round 17
// speedup vs baseline: 1.9974x; 1.0705x over previous
#include <cuda_runtime.h>
#include <cuda_fp16.h>
#include <cuda_bf16.h>
#include <cstdint>

#define N_NODES 100000
#define MAX_E   1600000
#define NB_SCAN 98             // ceil(100000/1024)
#define XCONV_BLOCKS 3125      // 800k threads, 8 floats each = 1.6M float4
#define APAD 72                // smem row stride in halves (144 B = 9*16B)

// ---------------- scratch (static device globals; no allocation) ------------
__device__ __align__(16) int     g_degi[N_NODES];        // zeroed by scan kernel each run
__device__ __align__(16) int     g_rowptr[N_NODES + 1];
__device__ __align__(16) int     g_fill[N_NODES];
__device__ __align__(16) int     g_blocksum[NB_SCAN + 1];
__device__ int                   g_arrive;               // scan rendezvous (0 at entry/exit)
__device__ int                   g_depart;
__device__ __align__(16) int     g_csr_src[MAX_E];
__device__ __align__(16) __half2 g_xh[N_NODES * 32];     // fp16 copy of x
__device__ __align__(16) __half2 g_meanh[N_NODES * 32];  // fp16 neighbor mean
__device__ __align__(16) __half  g_w1lh[64 * 64];
__device__ __align__(16) __half  g_w1rh[64 * 64];
__device__ __align__(16) __half  g_w2h[64 * 64];         // rows 0-31 W2l, 32-63 W2r
__device__ __align__(16) __half  g_ph[N_NODES * 32];     // h @ W2l^T (fp16)

__device__ __forceinline__ uint32_t smem_u32(const void* p) {
    return (uint32_t)__cvta_generic_to_shared(p);
}

// ---------------- K1: degree count || weights->fp16 || x->fp16 --------------
__global__ __launch_bounds__(256) void count_conv_kernel(
    const int* __restrict__ ei1, const int* __restrict__ ei2, int E1, int E2,
    const float* __restrict__ W1l, const float* __restrict__ W1r,
    const float* __restrict__ W2l, const float* __restrict__ W2r,
    const float4* __restrict__ x4, int nEdgeBlocks)
{
    int bid = blockIdx.x;
    if (bid < nEdgeBlocks) {
        int t = bid * 256 + threadIdx.x;
        int E = E1 + E2;
        if (t >= E) return;
        int d = (t < E1) ? ei1[t + E1] : ei2[(t - E1) + E2];
        atomicAdd(&g_degi[d], 1);
    } else if (bid == nEdgeBlocks) {
        int t = threadIdx.x;
        for (int i = t; i < 4096; i += 256) {
            g_w1lh[i] = __float2half_rn(W1l[i]);
            g_w1rh[i] = __float2half_rn(W1r[i]);
        }
        for (int i = t; i < 2048; i += 256) {
            g_w2h[i]        = __float2half_rn(W2l[i]);   // rows 0..31
            g_w2h[2048 + i] = __float2half_rn(W2r[i]);   // rows 32..63
        }
    } else {
        int t = (bid - nEdgeBlocks - 1) * 256 + threadIdx.x;   // < 800000
        float4 va = x4[2 * t], vb = x4[2 * t + 1];
        __half2 h0 = __floats2half2_rn(va.x, va.y);
        __half2 h1 = __floats2half2_rn(va.z, va.w);
        __half2 h2 = __floats2half2_rn(vb.x, vb.y);
        __half2 h3 = __floats2half2_rn(vb.z, vb.w);
        uint4 v;
        v.x = *reinterpret_cast<uint32_t*>(&h0);
        v.y = *reinterpret_cast<uint32_t*>(&h1);
        v.z = *reinterpret_cast<uint32_t*>(&h2);
        v.w = *reinterpret_cast<uint32_t*>(&h3);
        reinterpret_cast<uint4*>(g_xh)[t] = v;
    }
}

// ---------------- K2: fused exclusive scan (single launch, 98 blocks) -------
__global__ __launch_bounds__(256) void scan_fused_kernel(int E)
{
    __shared__ int swarp[8];
    __shared__ int soff;
    int tid = threadIdx.x, lane = tid & 31, wid = tid >> 5;
    int bid = blockIdx.x;
    int base = bid * 1024 + tid * 4;

    int v0 = (base + 0 < N_NODES) ? g_degi[base + 0] : 0;
    int v1 = (base + 1 < N_NODES) ? g_degi[base + 1] : 0;
    int v2 = (base + 2 < N_NODES) ? g_degi[base + 2] : 0;
    int v3 = (base + 3 < N_NODES) ? g_degi[base + 3] : 0;
    int tsum = v0 + v1 + v2 + v3;

    if (base + 0 < N_NODES) g_degi[base + 0] = 0;
    if (base + 1 < N_NODES) g_degi[base + 1] = 0;
    if (base + 2 < N_NODES) g_degi[base + 2] = 0;
    if (base + 3 < N_NODES) g_degi[base + 3] = 0;

    int s = tsum;
    #pragma unroll
    for (int off = 1; off < 32; off <<= 1) {
        int t = __shfl_up_sync(0xffffffffu, s, off);
        if (lane >= off) s += t;
    }
    if (lane == 31) swarp[wid] = s;
    __syncthreads();
    if (tid == 0) {
        int r = 0;
        #pragma unroll
        for (int i = 0; i < 8; i++) { int t = swarp[i]; swarp[i] = r; r += t; }
        g_blocksum[bid] = r;
        __threadfence();
        atomicAdd(&g_arrive, 1);
        while (atomicAdd(&g_arrive, 0) < NB_SCAN) { }   // rendezvous
    }
    __syncthreads();

    if (tid < 32) {
        int r = 0;
        for (int i = tid; i < bid; i += 32) r += g_blocksum[i];
        #pragma unroll
        for (int off = 16; off > 0; off >>= 1)
            r += __shfl_down_sync(0xffffffffu, r, off);
        if (tid == 0) soff = r;
    }
    __syncthreads();

    int excl = s - tsum + swarp[wid] + soff;
    if (base + 0 < N_NODES) { g_rowptr[base + 0] = excl;                g_fill[base + 0] = excl; }
    if (base + 1 < N_NODES) { g_rowptr[base + 1] = excl + v0;           g_fill[base + 1] = excl + v0; }
    if (base + 2 < N_NODES) { g_rowptr[base + 2] = excl + v0 + v1;      g_fill[base + 2] = excl + v0 + v1; }
    if (base + 3 < N_NODES) { g_rowptr[base + 3] = excl + v0 + v1 + v2; g_fill[base + 3] = excl + v0 + v1 + v2; }
    if (tid == 0 && bid == NB_SCAN - 1) g_rowptr[N_NODES] = E;

    __syncthreads();
    if (tid == 0) {
        int d = atomicAdd(&g_depart, 1);
        if (d == NB_SCAN - 1) { g_arrive = 0; g_depart = 0; }
    }
}

// ---------------- K3: fill CSR slots -----------------------------------------
__global__ __launch_bounds__(256) void fill_csr_kernel(
    const int* __restrict__ ei1, const int* __restrict__ ei2, int E1, int E2)
{
    int t = blockIdx.x * blockDim.x + threadIdx.x;
    int E = E1 + E2;
    if (t >= E) return;
    int s, d;
    if (t < E1) { s = ei1[t];      d = ei1[t + E1]; }
    else        { int u = t - E1;  s = ei2[u];  d = ei2[u + E2]; }
    int pos = atomicAdd(&g_fill[d], 1);
    g_csr_src[pos] = s;
}

// ---------------- K4: gather layer 1 (warp/node, 2 edges/step, HADD2 pair) --
// Lane layout: c = lane&15 (uint2 chunk: 4 halves), slot = lane>>4 (edge slot).
__global__ __launch_bounds__(256) void gather64_kernel()
{
    int wid = threadIdx.x >> 5, lane = threadIdx.x & 31;
    int n = blockIdx.x * 8 + wid;
    if (n >= N_NODES) return;                 // warp-uniform

    int start = g_rowptr[n], end = g_rowptr[n + 1];
    int c = lane & 15, slot = lane >> 4;
    const uint2* xrow = reinterpret_cast<const uint2*>(g_xh);   // row stride 16

    float a0 = 0.f, a1 = 0.f, a2 = 0.f, a3 = 0.f;

    for (int base = start; base < end; base += 32) {
        int t = base + lane;
        int sidx = (t < end) ? g_csr_src[t] : 0;   // coalesced, 32 edges/window
        int m = end - base; if (m > 32) m = 32;
        int j = 0;
        // 4-edge groups: two 2-edge steps, fp16 pairwise pre-add
        for (; j + 4 <= m; j += 4) {
            int sA = __shfl_sync(0xffffffffu, sidx, j + slot);
            int sB = __shfl_sync(0xffffffffu, sidx, j + 2 + slot);
            uint2 uA = __ldg(&xrow[sA * 16 + c]);
            uint2 uB = __ldg(&xrow[sB * 16 + c]);
            __half2 p0 = __hadd2(*reinterpret_cast<__half2*>(&uA.x),
                                 *reinterpret_cast<__half2*>(&uB.x));
            __half2 p1 = __hadd2(*reinterpret_cast<__half2*>(&uA.y),
                                 *reinterpret_cast<__half2*>(&uB.y));
            float2 f0 = __half22float2(p0);
            float2 f1 = __half22float2(p1);
            a0 += f0.x; a1 += f0.y; a2 += f1.x; a3 += f1.y;
        }
        if (j + 2 <= m) {        // 2-edge step, direct convert
            int sA = __shfl_sync(0xffffffffu, sidx, j + slot);
            uint2 uA = __ldg(&xrow[sA * 16 + c]);
            float2 f0 = __half22float2(*reinterpret_cast<__half2*>(&uA.x));
            float2 f1 = __half22float2(*reinterpret_cast<__half2*>(&uA.y));
            a0 += f0.x; a1 += f0.y; a2 += f1.x; a3 += f1.y;
            j += 2;
        }
        if (j < m) {             // single tail edge: lo half only
            int sA = __shfl_sync(0xffffffffu, sidx, j);
            if (slot == 0) {
                uint2 uA = __ldg(&xrow[sA * 16 + c]);
                float2 f0 = __half22float2(*reinterpret_cast<__half2*>(&uA.x));
                float2 f1 = __half22float2(*reinterpret_cast<__half2*>(&uA.y));
                a0 += f0.x; a1 += f0.y; a2 += f1.x; a3 += f1.y;
            }
        }
    }
    // combine the two edge slots
    a0 += __shfl_xor_sync(0xffffffffu, a0, 16);
    a1 += __shfl_xor_sync(0xffffffffu, a1, 16);
    a2 += __shfl_xor_sync(0xffffffffu, a2, 16);
    a3 += __shfl_xor_sync(0xffffffffu, a3, 16);

    float dinv = (end > start) ? 1.0f / (float)(end - start) : 0.0f;
    if (slot == 0) {
        __half2 h0 = __floats2half2_rn(a0 * dinv, a1 * dinv);
        __half2 h1 = __floats2half2_rn(a2 * dinv, a3 * dinv);
        uint2 o;
        o.x = *reinterpret_cast<uint32_t*>(&h0);
        o.y = *reinterpret_cast<uint32_t*>(&h1);
        reinterpret_cast<uint2*>(g_meanh)[n * 16 + c] = o;
    }
}

// ---------------- K5: fused two-layer GEMM on tensor cores (HMMA) -----------
__global__ __launch_bounds__(256) void fused_mma_kernel(
    const float* __restrict__ b1, const float* __restrict__ b2,
    float* __restrict__ out)
{
    __shared__ __half sA[128 * APAD];   // operand / h tile (18432 B)
    __shared__ __half sW[64 * APAD];    // weight tile (9216 B)
    __shared__ float  sb1[64];
    __shared__ float  sb2[32];

    int tid = threadIdx.x;
    int warp = tid >> 5, lane = tid & 31;
    int grp = lane >> 2, tig = lane & 3;
    int node0 = blockIdx.x * 128;

    if (tid < 64) sb1[tid] = b1[tid];
    if (tid >= 64 && tid < 96) sb2[tid - 64] = b2[tid - 64];

    int a_row  = lane & 15;
    int a_koff = (lane >> 4) * 8;
    int b_row  = lane & 7;
    int b_koff = ((lane >> 3) & 1) * 8;

    uint32_t a_base = smem_u32(&sA[(warp * 16 + a_row) * APAD + a_koff]);
    uint32_t b_base = smem_u32(&sW[b_row * APAD + b_koff]);

    float acc[8][4] = {};

    // ---------------- layer 1: two K=64 stages ------------------------------
    #pragma unroll
    for (int stage = 0; stage < 2; stage++) {
        const uint4* Asrc = reinterpret_cast<const uint4*>(stage ? g_xh : g_meanh);
        const uint4* Wsrc = reinterpret_cast<const uint4*>(stage ? g_w1rh : g_w1lh);
        #pragma unroll
        for (int i = 0; i < 4; i++) {                  // A: 128 rows x 8 uint4
            int idx = tid + i * 256;
            int n = idx >> 3, c = idx & 7;
            int gn = node0 + n;
            uint4 v = (gn < N_NODES) ? Asrc[gn * 8 + c] : make_uint4(0, 0, 0, 0);
            *reinterpret_cast<uint4*>(&sA[n * APAD + c * 8]) = v;
        }
        #pragma unroll
        for (int i = 0; i < 2; i++) {                  // W: 64 rows x 8 uint4
            int idx = tid + i * 256;
            int j = idx >> 3, c = idx & 7;
            *reinterpret_cast<uint4*>(&sW[j * APAD + c * 8]) = Wsrc[j * 8 + c];
        }
        __syncthreads();

        #pragma unroll
        for (int k0 = 0; k0 < 64; k0 += 16) {
            uint32_t a0, a1, a2, a3;
            asm volatile(
                "ldmatrix.sync.aligned.m8n8.x4.shared.b16 {%0,%1,%2,%3}, [%4];"
                : "=r"(a0), "=r"(a1), "=r"(a2), "=r"(a3)
                : "r"(a_base + k0 * 2));
            #pragma unroll
            for (int nt = 0; nt < 8; nt++) {
                uint32_t w0, w1;
                asm volatile(
                    "ldmatrix.sync.aligned.m8n8.x2.shared.b16 {%0,%1}, [%2];"
                    : "=r"(w0), "=r"(w1)
                    : "r"(b_base + (nt * 8 * APAD + k0) * 2));
                asm volatile(
                    "mma.sync.aligned.m16n8k16.row.col.f32.f16.f16.f32 "
                    "{%0,%1,%2,%3}, {%4,%5,%6,%7}, {%8,%9}, {%0,%1,%2,%3};"
                    : "+f"(acc[nt][0]), "+f"(acc[nt][1]),
                      "+f"(acc[nt][2]), "+f"(acc[nt][3])
                    : "r"(a0), "r"(a1), "r"(a2), "r"(a3), "r"(w0), "r"(w1));
            }
        }
        __syncthreads();
    }

    // ---------------- h = relu(acc + b1) -> sA (fp16, [node][k]) ------------
    #pragma unroll
    for (int nt = 0; nt < 8; nt++) {
        int feat = nt * 8 + tig * 2;
        float bx = sb1[feat], by = sb1[feat + 1];
        int r0 = warp * 16 + grp;
        __half2 h01 = __floats2half2_rn(fmaxf(acc[nt][0] + bx, 0.f),
                                        fmaxf(acc[nt][1] + by, 0.f));
        __half2 h23 = __floats2half2_rn(fmaxf(acc[nt][2] + bx, 0.f),
                                        fmaxf(acc[nt][3] + by, 0.f));
        *reinterpret_cast<__half2*>(&sA[r0 * APAD + feat]) = h01;
        *reinterpret_cast<__half2*>(&sA[(r0 + 8) * APAD + feat]) = h23;
        acc[nt][0] = acc[nt][1] = acc[nt][2] = acc[nt][3] = 0.f;
    }
    // load stacked W2
    #pragma unroll
    for (int i = 0; i < 2; i++) {
        int idx = tid + i * 256;
        int j = idx >> 3, c = idx & 7;
        *reinterpret_cast<uint4*>(&sW[j * APAD + c * 8]) =
            reinterpret_cast<const uint4*>(g_w2h)[j * 8 + c];
    }
    __syncthreads();

    // ---------------- layer 2: K=64 -----------------------------------------
    #pragma unroll
    for (int k0 = 0; k0 < 64; k0 += 16) {
        uint32_t a0, a1, a2, a3;
        asm volatile(
            "ldmatrix.sync.aligned.m8n8.x4.shared.b16 {%0,%1,%2,%3}, [%4];"
            : "=r"(a0), "=r"(a1), "=r"(a2), "=r"(a3)
            : "r"(a_base + k0 * 2));
        #pragma unroll
        for (int nt = 0; nt < 8; nt++) {
            uint32_t w0, w1;
            asm volatile(
                "ldmatrix.sync.aligned.m8n8.x2.shared.b16 {%0,%1}, [%2];"
                : "=r"(w0), "=r"(w1)
                : "r"(b_base + (nt * 8 * APAD + k0) * 2));
            asm volatile(
                "mma.sync.aligned.m16n8k16.row.col.f32.f16.f16.f32 "
                "{%0,%1,%2,%3}, {%4,%5,%6,%7}, {%8,%9}, {%0,%1,%2,%3};"
                : "+f"(acc[nt][0]), "+f"(acc[nt][1]),
                  "+f"(acc[nt][2]), "+f"(acc[nt][3])
                : "r"(a0), "r"(a1), "r"(a2), "r"(a3), "r"(w0), "r"(w1));
        }
    }

    // ------- store: cols 0-31 -> g_ph (fp16), 32-63 -> out (fp32 + b2) ------
    #pragma unroll
    for (int nt = 0; nt < 8; nt++) {
        int col = nt * 8 + tig * 2;
        int r0 = node0 + warp * 16 + grp;
        int r1 = r0 + 8;
        if (col < 32) {
            if (r0 < N_NODES)
                reinterpret_cast<__half2*>(g_ph)[r0 * 16 + (col >> 1)] =
                    __floats2half2_rn(acc[nt][0], acc[nt][1]);
            if (r1 < N_NODES)
                reinterpret_cast<__half2*>(g_ph)[r1 * 16 + (col >> 1)] =
                    __floats2half2_rn(acc[nt][2], acc[nt][3]);
        } else {
            int cc = col - 32;
            float bx = sb2[cc], by = sb2[cc + 1];
            if (r0 < N_NODES)
                reinterpret_cast<float2*>(out)[r0 * 16 + (cc >> 1)] =
                    make_float2(acc[nt][0] + bx, acc[nt][1] + by);
            if (r1 < N_NODES)
                reinterpret_cast<float2*>(out)[r1 * 16 + (cc >> 1)] =
                    make_float2(acc[nt][2] + bx, acc[nt][3] + by);
        }
    }
}

// ---------------- K6: gather layer 2 (warp/node, 4 edges/step, HADD2 pair) --
// Lane layout: c = lane&7 (uint2 chunk: 4 halves of 32), slot = lane>>3 (0..3).
__global__ __launch_bounds__(256) void gather32_kernel(float* __restrict__ out)
{
    int wid = threadIdx.x >> 5, lane = threadIdx.x & 31;
    int n = blockIdx.x * 8 + wid;
    if (n >= N_NODES) return;                 // warp-uniform

    int start = g_rowptr[n], end = g_rowptr[n + 1];
    int c = lane & 7, slot = lane >> 3;
    const uint2* prow = reinterpret_cast<const uint2*>(g_ph);   // row stride 8

    float a0 = 0.f, a1 = 0.f, a2 = 0.f, a3 = 0.f;

    for (int base = start; base < end; base += 32) {
        int t = base + lane;
        int sidx = (t < end) ? g_csr_src[t] : 0;
        int m = end - base; if (m > 32) m = 32;
        int j = 0;
        // 8-edge groups: two 4-edge steps, fp16 pairwise pre-add
        for (; j + 8 <= m; j += 8) {
            int sA = __shfl_sync(0xffffffffu, sidx, j + slot);
            int sB = __shfl_sync(0xffffffffu, sidx, j + 4 + slot);
            uint2 uA = __ldg(&prow[sA * 8 + c]);
            uint2 uB = __ldg(&prow[sB * 8 + c]);
            __half2 p0 = __hadd2(*reinterpret_cast<__half2*>(&uA.x),
                                 *reinterpret_cast<__half2*>(&uB.x));
            __half2 p1 = __hadd2(*reinterpret_cast<__half2*>(&uA.y),
                                 *reinterpret_cast<__half2*>(&uB.y));
            float2 f0 = __half22float2(p0);
            float2 f1 = __half22float2(p1);
            a0 += f0.x; a1 += f0.y; a2 += f1.x; a3 += f1.y;
        }
        if (j + 4 <= m) {        // 4-edge step, direct convert
            int sA = __shfl_sync(0xffffffffu, sidx, j + slot);
            uint2 uA = __ldg(&prow[sA * 8 + c]);
            float2 f0 = __half22float2(*reinterpret_cast<__half2*>(&uA.x));
            float2 f1 = __half22float2(*reinterpret_cast<__half2*>(&uA.y));
            a0 += f0.x; a1 += f0.y; a2 += f1.x; a3 += f1.y;
            j += 4;
        }
        if (j < m) {             // 1..3 tail edges: slots < r participate
            int r = m - j;
            int src = j + (slot < r ? slot : 0);
            int sA = __shfl_sync(0xffffffffu, sidx, src);
            if (slot < r) {
                uint2 uA = __ldg(&prow[sA * 8 + c]);
                float2 f0 = __half22float2(*reinterpret_cast<__half2*>(&uA.x));
                float2 f1 = __half22float2(*reinterpret_cast<__half2*>(&uA.y));
                a0 += f0.x; a1 += f0.y; a2 += f1.x; a3 += f1.y;
            }
        }
    }
    // combine the four edge slots
    #pragma unroll
    for (int off = 8; off <= 16; off <<= 1) {
        a0 += __shfl_xor_sync(0xffffffffu, a0, off);
        a1 += __shfl_xor_sync(0xffffffffu, a1, off);
        a2 += __shfl_xor_sync(0xffffffffu, a2, off);
        a3 += __shfl_xor_sync(0xffffffffu, a3, off);
    }

    float dinv = (end > start) ? 1.0f / (float)(end - start) : 0.0f;
    if (slot == 0) {
        float4* op = reinterpret_cast<float4*>(&out[n * 32 + c * 4]);
        float4 cur = *op;
        cur.x += a0 * dinv; cur.y += a1 * dinv;
        cur.z += a2 * dinv; cur.w += a3 * dinv;
        *op = cur;
    }
}

// ---------------- launch ------------------------------------------------------
extern "C" void kernel_launch(void* const* d_in, const int* in_sizes, int n_in,
                              void* d_out, int out_size)
{
    const float* x    = (const float*)d_in[0];
    const int*   ei1  = (const int*)d_in[1];     // int32 (JAX x64 disabled)
    const int*   ei2  = (const int*)d_in[3];
    const float* W1l  = (const float*)d_in[5];
    const float* b1   = (const float*)d_in[6];
    const float* W1r  = (const float*)d_in[7];
    const float* W2l  = (const float*)d_in[8];
    const float* b2   = (const float*)d_in[9];
    const float* W2r  = (const float*)d_in[10];
    float*       out  = (float*)d_out;

    int E1 = in_sizes[1] / 2;
    int E2 = in_sizes[3] / 2;
    int E  = E1 + E2;
    int nEdgeBlocks = (E + 255) / 256;

    // K1: degree count || weight fp16 conversion || x fp16 conversion
    count_conv_kernel<<<nEdgeBlocks + 1 + XCONV_BLOCKS, 256>>>(
        ei1, ei2, E1, E2, W1l, W1r, W2l, W2r,
        reinterpret_cast<const float4*>(x), nEdgeBlocks);

    // K2: fused scan (single launch)
    scan_fused_kernel<<<NB_SCAN, 256>>>(E);

    // K3: fill CSR
    fill_csr_kernel<<<nEdgeBlocks, 256>>>(ei1, ei2, E1, E2);

    // K4: layer-1 aggregation (2 edges/step, fp16 pairwise)
    gather64_kernel<<<(N_NODES + 7) / 8, 256>>>();

    // K5: fused two-layer GEMM on tensor cores -> g_ph, out(self term)
    fused_mma_kernel<<<(N_NODES + 127) / 128, 256>>>(b1, b2, out);

    // K6: layer-2 aggregation (4 edges/step, fp16 pairwise)
    gather32_kernel<<<(N_NODES + 7) / 8, 256>>>(out);
}